// round 2
// baseline (speedup 1.0000x reference)
#include <cuda_runtime.h>
#include <math.h>

#define CDIV(a,b) (((a)+(b)-1)/(b))

namespace {
constexpr int NNODES = 50000;
constexpr int NEDGES = 300000;
constexpr int NTOT   = 100000;   // B * N_NODES
constexpr int K1P    = 528;      // 515 padded to multiple of 16
}

// ------------------------- static device scratch (~1.02 GB) -------------------------
__device__ float g_f0[16777216];      // (2,256,32^3)  conv0 out, (b,c,s)
__device__ float g_f1[4194304];       // (2,16^3,512)  conv1 out, (b,s,c) row-major GEMM C
__device__ float g_f2[4194304];       // (2,16^3,512)  conv2 out, (b,s,c)
__device__ float g_w1t[8388608];      // w1 transposed to (K=16384, N=512)
__device__ float g_w2t[7077888];      // w2 transposed to (K=13824, N=512)
__device__ float g_node[52800000];    // (100000, 528) padded node features
__device__ float g_wk1[135168];       // (528,256) padded weights
__device__ float g_wq1[135168];
__device__ float g_wv1[135168];
__device__ float g_ws1[135168];
__device__ float g_k1[25600000];
__device__ float g_q1[25600000];
__device__ float g_v1[25600000];
__device__ float g_h1[25600000];
__device__ float g_k2[12800000];
__device__ float g_q2[12800000];
__device__ float g_v2[12800000];
__device__ float g_h2[12800000];
__device__ float g_h3[6400000];
__device__ float g_scale[512];
__device__ float g_shift[512];

// ------------------------- conv0: direct 3x3x3, C_in=4 -------------------------
__global__ void conv0_kernel(const float* __restrict__ x, const float* __restrict__ w0) {
    __shared__ float ws[108];
    int co = blockIdx.y, b = blockIdx.z;
    if (threadIdx.x < 108) ws[threadIdx.x] = w0[co * 108 + threadIdx.x];
    __syncthreads();
    int s = blockIdx.x * 256 + threadIdx.x;
    int z = s >> 10, y = (s >> 5) & 31, xx = s & 31;
    float acc = 0.f;
    #pragma unroll
    for (int ci = 0; ci < 4; ci++) {
        const float* xb = x + ((size_t)(b * 4 + ci) << 15);
        const float* wc = ws + ci * 27;
        #pragma unroll
        for (int kd = 0; kd < 3; kd++) {
            int id = z + kd - 1;
            if ((unsigned)id > 31u) continue;
            #pragma unroll
            for (int kh = 0; kh < 3; kh++) {
                int ih = y + kh - 1;
                if ((unsigned)ih > 31u) continue;
                #pragma unroll
                for (int kw = 0; kw < 3; kw++) {
                    int iw = xx + kw - 1;
                    if ((unsigned)iw > 31u) continue;
                    acc = fmaf(xb[(id << 10) + (ih << 5) + iw], wc[kd * 9 + kh * 3 + kw], acc);
                }
            }
        }
    }
    g_f0[(((size_t)((b << 8) + co)) << 15) + s] = acc;
}

// ------------------------- batchnorm statistics -------------------------
// layout (b, c, s): channel data contiguous per batch
__global__ void bn_stats_bcs(const float* __restrict__ x, int C, int S, int Bn,
                             const float* __restrict__ gm, const float* __restrict__ bt) {
    int c = blockIdx.x;
    int total = Bn * S;
    double s1 = 0.0, s2 = 0.0;
    for (int e = threadIdx.x; e < total; e += blockDim.x) {
        int b = e / S, ss = e - b * S;
        float v = x[((size_t)(b * C + c)) * S + ss];
        s1 += v; s2 += (double)v * v;
    }
    __shared__ double r1[256], r2[256];
    int tid = threadIdx.x;
    r1[tid] = s1; r2[tid] = s2; __syncthreads();
    for (int o = 128; o; o >>= 1) {
        if (tid < o) { r1[tid] += r1[tid + o]; r2[tid] += r2[tid + o]; }
        __syncthreads();
    }
    if (tid == 0) {
        double mean = r1[0] / total;
        double var  = r2[0] / total - mean * mean;
        float sc = gm[c] * rsqrtf((float)var + 1e-5f);
        g_scale[c] = sc;
        g_shift[c] = bt[c] - (float)mean * sc;
    }
}

// layout (rows, C): channel stride 1 across row
__global__ void bn_stats_rc(const float* __restrict__ x, int C, int rows,
                            const float* __restrict__ gm, const float* __restrict__ bt) {
    int c = blockIdx.x;
    double s1 = 0.0, s2 = 0.0;
    for (int r = threadIdx.x; r < rows; r += blockDim.x) {
        float v = x[(size_t)r * C + c];
        s1 += v; s2 += (double)v * v;
    }
    __shared__ double r1[256], r2[256];
    int tid = threadIdx.x;
    r1[tid] = s1; r2[tid] = s2; __syncthreads();
    for (int o = 128; o; o >>= 1) {
        if (tid < o) { r1[tid] += r1[tid + o]; r2[tid] += r2[tid + o]; }
        __syncthreads();
    }
    if (tid == 0) {
        double mean = r1[0] / rows;
        double var  = r2[0] / rows - mean * mean;
        float sc = gm[c] * rsqrtf((float)var + 1e-5f);
        g_scale[c] = sc;
        g_shift[c] = bt[c] - (float)mean * sc;
    }
}

__global__ void bn_apply_bcs(float* __restrict__ x, int C, int S, int n, int do_relu) {
    int i = blockIdx.x * blockDim.x + threadIdx.x;
    if (i >= n) return;
    int c = (i / S) % C;
    float v = x[i] * g_scale[c] + g_shift[c];
    x[i] = do_relu ? fmaxf(v, 0.f) : v;
}

__global__ void bn_apply_rc(float* __restrict__ x, int C, int n, int do_relu) {
    int i = blockIdx.x * blockDim.x + threadIdx.x;
    if (i >= n) return;
    int c = i % C;
    float v = x[i] * g_scale[c] + g_shift[c];
    x[i] = do_relu ? fmaxf(v, 0.f) : v;
}

// ------------------------- weight transpose: (R rows, C cols) -> (C, R) -------------------------
__global__ void transpose_kernel(const float* __restrict__ src, float* __restrict__ dst,
                                 int R, int Ccols) {
    __shared__ float tile[32][33];
    int c0 = blockIdx.x * 32, r0 = blockIdx.y * 32;
    int x = threadIdx.x, y = threadIdx.y;
    for (int i = y; i < 32; i += 8) {
        int r = r0 + i, c = c0 + x;
        tile[i][x] = (r < R && c < Ccols) ? src[(size_t)r * Ccols + c] : 0.f;
    }
    __syncthreads();
    for (int i = y; i < 32; i += 8) {
        int c = c0 + i, r = r0 + x;
        if (c < Ccols && r < R) dst[(size_t)c * R + r] = tile[x][i];
    }
}

__global__ void pad_weight(const float* __restrict__ src, float* __restrict__ dst,
                           int Kin, int Kpad, int N) {
    int i = blockIdx.x * blockDim.x + threadIdx.x;
    if (i >= Kpad * N) return;
    int k = i / N, n = i - k * N;
    dst[i] = (k < Kin) ? src[k * N + n] : 0.f;
}

// ------------------------- GEMM: C[M,N] = A[M,K] @ B[K,N] (+bias)(+relu) -------------------------
// MODE 0: plain row-major A.  MODE 1: implicit im2col for conv1 (4^3 stride2 pad1 on (b,c,32^3)).
// MODE 2: implicit im2col for conv2 (3^3 stride1 pad1 on (b,16^3,c) layout).
template<int MODE>
__global__ void gemm_kernel(const float* __restrict__ A, const float* __restrict__ Bm,
                            float* __restrict__ C, int M, int N, int K,
                            const float* __restrict__ bias, int do_relu) {
    __shared__ float As[16][65];
    __shared__ float Bs[16][64];
    int tid = threadIdx.x;
    int bm = blockIdx.y * 64, bn = blockIdx.x * 64;
    int tx = tid & 15, ty = tid >> 4;
    float acc[4][4];
    #pragma unroll
    for (int i = 0; i < 4; i++)
        #pragma unroll
        for (int j = 0; j < 4; j++) acc[i][j] = 0.f;

    for (int k0 = 0; k0 < K; k0 += 16) {
        #pragma unroll
        for (int i = 0; i < 4; i++) {
            int l = tid + i * 256;
            int mm = l >> 4, kk = l & 15;
            int gm = bm + mm;
            float v = 0.f;
            if (gm < M) {
                int gk = k0 + kk;
                if (MODE == 0) {
                    v = A[(size_t)gm * K + gk];
                } else if (MODE == 1) {
                    int b = gm >> 12, s = gm & 4095;
                    int od = s >> 8, oh = (s >> 4) & 15, ow = s & 15;
                    int cc = gk >> 6, r = gk & 63;
                    int kd = r >> 4, kh = (r >> 2) & 3, kw = r & 3;
                    int id = od * 2 - 1 + kd, ih = oh * 2 - 1 + kh, iw = ow * 2 - 1 + kw;
                    if ((unsigned)id <= 31u && (unsigned)ih <= 31u && (unsigned)iw <= 31u)
                        v = A[(((size_t)((b << 8) + cc)) << 15) + (id << 10) + (ih << 5) + iw];
                } else {
                    int b = gm >> 12, s = gm & 4095;
                    int od = s >> 8, oh = (s >> 4) & 15, ow = s & 15;
                    int cc = gk / 27, r = gk - cc * 27;
                    int kd = r / 9; r -= kd * 9;
                    int kh = r / 3; int kw = r - kh * 3;
                    int id = od - 1 + kd, ih = oh - 1 + kh, iw = ow - 1 + kw;
                    if ((unsigned)id <= 15u && (unsigned)ih <= 15u && (unsigned)iw <= 15u)
                        v = A[((size_t)((b << 12) + (id << 8) + (ih << 4) + iw)) * 512 + cc];
                }
            }
            As[kk][mm] = v;
        }
        #pragma unroll
        for (int i = 0; i < 4; i++) {
            int l = tid + i * 256;
            int kk = l >> 6, nn = l & 63;
            Bs[kk][nn] = Bm[(size_t)(k0 + kk) * N + bn + nn];
        }
        __syncthreads();
        #pragma unroll
        for (int kk = 0; kk < 16; kk++) {
            float a[4], b4[4];
            #pragma unroll
            for (int i = 0; i < 4; i++) a[i] = As[kk][ty * 4 + i];
            #pragma unroll
            for (int j = 0; j < 4; j++) b4[j] = Bs[kk][tx * 4 + j];
            #pragma unroll
            for (int i = 0; i < 4; i++)
                #pragma unroll
                for (int j = 0; j < 4; j++)
                    acc[i][j] = fmaf(a[i], b4[j], acc[i][j]);
        }
        __syncthreads();
    }
    #pragma unroll
    for (int i = 0; i < 4; i++) {
        int gm = bm + ty * 4 + i;
        if (gm >= M) continue;
        #pragma unroll
        for (int j = 0; j < 4; j++) {
            int gn = bn + tx * 4 + j;
            float v = acc[i][j];
            if (bias) v += bias[gn];
            if (do_relu) v = fmaxf(v, 0.f);
            C[(size_t)gm * N + gn] = v;
        }
    }
}

// ------------------------- node feature gather -------------------------
__global__ void node_gather(const float* __restrict__ pos) {
    int r = blockIdx.x;
    int b = r / NNODES, n = r - b * NNODES;
    float p0 = pos[n * 3], p1 = pos[n * 3 + 1], p2 = pos[n * 3 + 2];
    int i0 = (int)(p0 * 16.f - 1.f);
    int i1 = (int)(p1 * 16.f - 1.f);
    int i2 = (int)(p2 * 16.f - 1.f);
    int vox = (i0 << 8) + (i1 << 4) + i2;
    const float* src = g_f2 + ((size_t)((b << 12) + vox)) * 512;
    float* drow = g_node + (size_t)r * K1P;
    for (int c = threadIdx.x; c < K1P; c += blockDim.x) {
        float v;
        if (c < 3)        v = (c == 0) ? p0 : ((c == 1) ? p1 : p2);
        else if (c < 515) v = src[c - 3];
        else              v = 0.f;
        drow[c] = v;
    }
}

// ------------------------- gated edge messages + segment sum -------------------------
__global__ void edge_kernel(const float* __restrict__ kf, const float* __restrict__ qf,
                            const float* __restrict__ vf, float* __restrict__ hf,
                            const int* __restrict__ ei, int F) {
    int j = blockIdx.x;                 // 0 .. 2*NEDGES-1
    int b = (j >= NEDGES) ? 1 : 0;
    int e = j - b * NEDGES;
    int src = ei[e] + b * NNODES;
    int dst = ei[NEDGES + e] + b * NNODES;
    int c = threadIdx.x;
    float kv = kf[(size_t)dst * F + c];
    float qv = qf[(size_t)src * F + c];
    float vv = vf[(size_t)src * F + c];
    float g = 1.f / (1.f + expf(-(kv + qv)));
    atomicAdd(&hf[(size_t)dst * F + c], g * vv);
}

__global__ void relu_kernel(float* __restrict__ x, int n) {
    int i = blockIdx.x * blockDim.x + threadIdx.x;
    if (i < n) x[i] = fmaxf(x[i], 0.f);
}

// ------------------------- final small MLP layer (N=3) -------------------------
__global__ void mlp2_kernel(const float* __restrict__ w, const float* __restrict__ bb,
                            float* __restrict__ out) {
    int r = blockIdx.x * blockDim.x + threadIdx.x;
    if (r >= NTOT) return;
    const float* row = g_h3 + (size_t)r * 64;
    float a0 = bb[0], a1 = bb[1], a2 = bb[2];
    #pragma unroll
    for (int k = 0; k < 64; k++) {
        float xv = row[k];
        a0 = fmaf(xv, __ldg(&w[k * 3 + 0]), a0);
        a1 = fmaf(xv, __ldg(&w[k * 3 + 1]), a1);
        a2 = fmaf(xv, __ldg(&w[k * 3 + 2]), a2);
    }
    out[r * 3 + 0] = fmaxf(a0, 0.f);
    out[r * 3 + 1] = fmaxf(a1, 0.f);
    out[r * 3 + 2] = fmaxf(a2, 0.f);
}

// ------------------------- launcher -------------------------
extern "C" void kernel_launch(void* const* d_in, const int* in_sizes, int n_in,
                              void* d_out, int out_size) {
    const float* x   = (const float*)d_in[0];
    const float* pos = (const float*)d_in[1];
    const float* w0  = (const float*)d_in[2];
    const float* g0  = (const float*)d_in[3];
    const float* b0  = (const float*)d_in[4];
    const float* w1  = (const float*)d_in[5];
    const float* g1  = (const float*)d_in[6];
    const float* b1  = (const float*)d_in[7];
    const float* w2  = (const float*)d_in[8];
    const float* g2  = (const float*)d_in[9];
    const float* b2  = (const float*)d_in[10];
    const float* gk1 = (const float*)d_in[11];
    const float* gq1 = (const float*)d_in[12];
    const float* gv1 = (const float*)d_in[13];
    const float* gs1 = (const float*)d_in[14];
    const float* gb1 = (const float*)d_in[15];
    const float* gk2 = (const float*)d_in[16];
    const float* gq2 = (const float*)d_in[17];
    const float* gv2 = (const float*)d_in[18];
    const float* gs2 = (const float*)d_in[19];
    const float* gb2 = (const float*)d_in[20];
    const float* m1w = (const float*)d_in[21];
    const float* m1b = (const float*)d_in[22];
    const float* m2w = (const float*)d_in[23];
    const float* m2b = (const float*)d_in[24];
    const int*   ei  = (const int*)d_in[25];
    float* out = (float*)d_out;

    float *p_f0, *p_f1, *p_f2, *p_w1t, *p_w2t, *p_node;
    float *p_wk1, *p_wq1, *p_wv1, *p_ws1;
    float *p_k1, *p_q1, *p_v1, *p_h1, *p_k2, *p_q2, *p_v2, *p_h2, *p_h3;
    cudaGetSymbolAddress((void**)&p_f0,  g_f0);
    cudaGetSymbolAddress((void**)&p_f1,  g_f1);
    cudaGetSymbolAddress((void**)&p_f2,  g_f2);
    cudaGetSymbolAddress((void**)&p_w1t, g_w1t);
    cudaGetSymbolAddress((void**)&p_w2t, g_w2t);
    cudaGetSymbolAddress((void**)&p_node, g_node);
    cudaGetSymbolAddress((void**)&p_wk1, g_wk1);
    cudaGetSymbolAddress((void**)&p_wq1, g_wq1);
    cudaGetSymbolAddress((void**)&p_wv1, g_wv1);
    cudaGetSymbolAddress((void**)&p_ws1, g_ws1);
    cudaGetSymbolAddress((void**)&p_k1,  g_k1);
    cudaGetSymbolAddress((void**)&p_q1,  g_q1);
    cudaGetSymbolAddress((void**)&p_v1,  g_v1);
    cudaGetSymbolAddress((void**)&p_h1,  g_h1);
    cudaGetSymbolAddress((void**)&p_k2,  g_k2);
    cudaGetSymbolAddress((void**)&p_q2,  g_q2);
    cudaGetSymbolAddress((void**)&p_v2,  g_v2);
    cudaGetSymbolAddress((void**)&p_h2,  g_h2);
    cudaGetSymbolAddress((void**)&p_h3,  g_h3);

    // conv0 + bn + relu   (f0: (b,c,32^3))
    conv0_kernel<<<dim3(128, 256, 2), 256>>>(x, w0);
    bn_stats_bcs<<<256, 256>>>(p_f0, 256, 32768, 2, g0, b0);
    bn_apply_bcs<<<CDIV(16777216, 256), 256>>>(p_f0, 256, 32768, 16777216, 1);

    // transpose conv weights to (K, N)
    transpose_kernel<<<dim3(16384 / 32, 512 / 32), dim3(32, 8)>>>(w1, p_w1t, 512, 16384);
    transpose_kernel<<<dim3(13824 / 32, 512 / 32), dim3(32, 8)>>>(w2, p_w2t, 512, 13824);

    // conv1 (implicit GEMM) + bn + relu   (f1: (b,16^3,512))
    gemm_kernel<1><<<dim3(8, 128), 256>>>(p_f0, p_w1t, p_f1, 8192, 512, 16384, nullptr, 0);
    bn_stats_rc<<<512, 256>>>(p_f1, 512, 8192, g1, b1);
    bn_apply_rc<<<CDIV(4194304, 256), 256>>>(p_f1, 512, 4194304, 1);

    // conv2 (implicit GEMM) + bn (no relu)
    gemm_kernel<2><<<dim3(8, 128), 256>>>(p_f1, p_w2t, p_f2, 8192, 512, 13824, nullptr, 0);
    bn_stats_rc<<<512, 256>>>(p_f2, 512, 8192, g2, b2);
    bn_apply_rc<<<CDIV(4194304, 256), 256>>>(p_f2, 512, 4194304, 0);

    // node features (pos ++ sampled f2), padded to 528
    node_gather<<<NTOT, 128>>>(pos);

    // pad GNN layer-1 weights to K=528
    pad_weight<<<CDIV(K1P * 256, 256), 256>>>(gk1, p_wk1, 515, K1P, 256);
    pad_weight<<<CDIV(K1P * 256, 256), 256>>>(gq1, p_wq1, 515, K1P, 256);
    pad_weight<<<CDIV(K1P * 256, 256), 256>>>(gv1, p_wv1, 515, K1P, 256);
    pad_weight<<<CDIV(K1P * 256, 256), 256>>>(gs1, p_ws1, 515, K1P, 256);

    // GNN layer 1
    dim3 gridG1(4, CDIV(NTOT, 64));
    gemm_kernel<0><<<gridG1, 256>>>(p_node, p_wk1, p_k1, NTOT, 256, K1P, nullptr, 0);
    gemm_kernel<0><<<gridG1, 256>>>(p_node, p_wq1, p_q1, NTOT, 256, K1P, nullptr, 0);
    gemm_kernel<0><<<gridG1, 256>>>(p_node, p_wv1, p_v1, NTOT, 256, K1P, nullptr, 0);
    gemm_kernel<0><<<gridG1, 256>>>(p_node, p_ws1, p_h1, NTOT, 256, K1P, gb1, 0);
    edge_kernel<<<2 * NEDGES, 256>>>(p_k1, p_q1, p_v1, p_h1, ei, 256);
    relu_kernel<<<CDIV(25600000, 256), 256>>>(p_h1, 25600000);

    // GNN layer 2
    dim3 gridG2(2, CDIV(NTOT, 64));
    gemm_kernel<0><<<gridG2, 256>>>(p_h1, gk2, p_k2, NTOT, 128, 256, nullptr, 0);
    gemm_kernel<0><<<gridG2, 256>>>(p_h1, gq2, p_q2, NTOT, 128, 256, nullptr, 0);
    gemm_kernel<0><<<gridG2, 256>>>(p_h1, gv2, p_v2, NTOT, 128, 256, nullptr, 0);
    gemm_kernel<0><<<gridG2, 256>>>(p_h1, gs2, p_h2, NTOT, 128, 256, gb2, 0);
    edge_kernel<<<2 * NEDGES, 128>>>(p_k2, p_q2, p_v2, p_h2, ei, 128);
    relu_kernel<<<CDIV(12800000, 256), 256>>>(p_h2, 12800000);

    // MLP head
    gemm_kernel<0><<<dim3(1, CDIV(NTOT, 64)), 256>>>(p_h2, m1w, p_h3, NTOT, 64, 128, m1b, 1);
    mlp2_kernel<<<CDIV(NTOT, 256), 256>>>(m2w, m2b, out);
}

// round 3
// speedup vs baseline: 2.1229x; 2.1229x over previous
#include <cuda_runtime.h>
#include <math.h>

#define CDIV(a,b) (((a)+(b)-1)/(b))

namespace {
constexpr int NNODES = 50000;
constexpr int NEDGES = 300000;
constexpr int NTOT   = 100000;   // B * N_NODES
constexpr int K1P    = 544;      // 515 padded to multiple of 32
}

// ------------------------- static device scratch -------------------------
__device__ float g_f0[16777216];       // (2,256,32^3)  conv0 out, (b,c,s)
__device__ float g_f1[4194304];        // (2,16^3,512)  conv1 out, (b,s,c)
__device__ float g_f2[4194304];        // (2,16^3,512)  conv2 out
__device__ float g_w1t[8388608];       // w1^T (16384, 512)
__device__ float g_w2t[7077888];       // w2^T (13824, 512)
__device__ float g_node[54400000];     // (100000, 544)
__device__ float g_wcat1[557056];      // (544, 1024) = [Wk|Wq|Wv|Ws] padded
__device__ float g_wcat2[131072];      // (256, 512)
__device__ float g_bias1[1024];
__device__ float g_bias2[512];
__device__ float g_kqvs1[102400000];   // (100000, 1024)
__device__ float g_kqvs2[51200000];    // (100000, 512)
__device__ float g_h3[6400000];        // (100000, 64)
__device__ float g_scale[512];
__device__ float g_shift[512];

__device__ __forceinline__ unsigned f2tf(float x) {
    unsigned r;
    asm("cvt.rna.tf32.f32 %0, %1;" : "=r"(r) : "f"(x));
    return r;
}

// ------------------------- conv0: direct 3x3x3, C_in=4 (fp32) -------------------------
__global__ void conv0_kernel(const float* __restrict__ x, const float* __restrict__ w0) {
    __shared__ float ws[108];
    int co = blockIdx.y, b = blockIdx.z;
    if (threadIdx.x < 108) ws[threadIdx.x] = w0[co * 108 + threadIdx.x];
    __syncthreads();
    int s = blockIdx.x * 256 + threadIdx.x;
    int z = s >> 10, y = (s >> 5) & 31, xx = s & 31;
    float acc = 0.f;
    #pragma unroll
    for (int ci = 0; ci < 4; ci++) {
        const float* xb = x + ((size_t)(b * 4 + ci) << 15);
        const float* wc = ws + ci * 27;
        #pragma unroll
        for (int kd = 0; kd < 3; kd++) {
            int id = z + kd - 1;
            if ((unsigned)id > 31u) continue;
            #pragma unroll
            for (int kh = 0; kh < 3; kh++) {
                int ih = y + kh - 1;
                if ((unsigned)ih > 31u) continue;
                #pragma unroll
                for (int kw = 0; kw < 3; kw++) {
                    int iw = xx + kw - 1;
                    if ((unsigned)iw > 31u) continue;
                    acc = fmaf(xb[(id << 10) + (ih << 5) + iw], wc[kd * 9 + kh * 3 + kw], acc);
                }
            }
        }
    }
    g_f0[(((size_t)((b << 8) + co)) << 15) + s] = acc;
}

// ------------------------- batchnorm -------------------------
__global__ void bn_stats_bcs(const float* __restrict__ x, int C, int S, int Bn,
                             const float* __restrict__ gm, const float* __restrict__ bt) {
    int c = blockIdx.x;
    int total = Bn * S;
    double s1 = 0.0, s2 = 0.0;
    for (int e = threadIdx.x; e < total; e += blockDim.x) {
        int b = e / S, ss = e - b * S;
        float v = x[((size_t)(b * C + c)) * S + ss];
        s1 += v; s2 += (double)v * v;
    }
    __shared__ double r1[256], r2[256];
    int tid = threadIdx.x;
    r1[tid] = s1; r2[tid] = s2; __syncthreads();
    for (int o = 128; o; o >>= 1) {
        if (tid < o) { r1[tid] += r1[tid + o]; r2[tid] += r2[tid + o]; }
        __syncthreads();
    }
    if (tid == 0) {
        double mean = r1[0] / total;
        double var  = r2[0] / total - mean * mean;
        float sc = gm[c] * rsqrtf((float)var + 1e-5f);
        g_scale[c] = sc;
        g_shift[c] = bt[c] - (float)mean * sc;
    }
}

__global__ void bn_stats_rc(const float* __restrict__ x, int C, int rows,
                            const float* __restrict__ gm, const float* __restrict__ bt) {
    int c = blockIdx.x;
    double s1 = 0.0, s2 = 0.0;
    for (int r = threadIdx.x; r < rows; r += blockDim.x) {
        float v = x[(size_t)r * C + c];
        s1 += v; s2 += (double)v * v;
    }
    __shared__ double r1[256], r2[256];
    int tid = threadIdx.x;
    r1[tid] = s1; r2[tid] = s2; __syncthreads();
    for (int o = 128; o; o >>= 1) {
        if (tid < o) { r1[tid] += r1[tid + o]; r2[tid] += r2[tid + o]; }
        __syncthreads();
    }
    if (tid == 0) {
        double mean = r1[0] / rows;
        double var  = r2[0] / rows - mean * mean;
        float sc = gm[c] * rsqrtf((float)var + 1e-5f);
        g_scale[c] = sc;
        g_shift[c] = bt[c] - (float)mean * sc;
    }
}

__global__ void bn_apply_bcs(float* __restrict__ x, int C, int S, int n, int do_relu) {
    int i = blockIdx.x * blockDim.x + threadIdx.x;
    if (i >= n) return;
    int c = (i / S) % C;
    float v = x[i] * g_scale[c] + g_shift[c];
    x[i] = do_relu ? fmaxf(v, 0.f) : v;
}

__global__ void bn_apply_rc(float* __restrict__ x, int C, int n, int do_relu) {
    int i = blockIdx.x * blockDim.x + threadIdx.x;
    if (i >= n) return;
    int c = i % C;
    float v = x[i] * g_scale[c] + g_shift[c];
    x[i] = do_relu ? fmaxf(v, 0.f) : v;
}

// ------------------------- weight prep -------------------------
__global__ void transpose_kernel(const float* __restrict__ src, float* __restrict__ dst,
                                 int R, int Ccols) {
    __shared__ float tile[32][33];
    int c0 = blockIdx.x * 32, r0 = blockIdx.y * 32;
    int x = threadIdx.x, y = threadIdx.y;
    for (int i = y; i < 32; i += 8) {
        int r = r0 + i, c = c0 + x;
        tile[i][x] = (r < R && c < Ccols) ? src[(size_t)r * Ccols + c] : 0.f;
    }
    __syncthreads();
    for (int i = y; i < 32; i += 8) {
        int c = c0 + i, r = r0 + x;
        if (c < Ccols && r < R) dst[(size_t)c * R + r] = tile[x][i];
    }
}

// dst[k * Nout + colOff + f] = (k < Kin) ? src[k * F + f] : 0
__global__ void concat_weight(const float* __restrict__ src, float* __restrict__ dst,
                              int Kin, int Kpad, int F, int colOff, int Nout) {
    int i = blockIdx.x * blockDim.x + threadIdx.x;
    if (i >= Kpad * F) return;
    int k = i / F, f = i - k * F;
    dst[(size_t)k * Nout + colOff + f] = (k < Kin) ? src[k * F + f] : 0.f;
}

__global__ void build_bias(const float* __restrict__ src, float* __restrict__ dst,
                           int off, int F, int Nout) {
    int i = blockIdx.x * blockDim.x + threadIdx.x;
    if (i >= Nout) return;
    dst[i] = (i >= off && i < off + F) ? src[i - off] : 0.f;
}

// ------------------------- tf32 tensor-core GEMM -------------------------
// C[M,N] = A[M,K] @ B[K,N] (+bias)(+relu). BM=128, BN=128, BK=32, 256 threads.
// MODE 0: A row-major with leading dim lda.
// MODE 1: implicit im2col for conv1 (4^3 s2 p1 on (b,c,32^3)).
// MODE 2: implicit im2col for conv2 (3^3 s1 p1 on (b,16^3,c)).
template<int MODE>
__global__ void __launch_bounds__(256)
mma_gemm(const float* __restrict__ A, const float* __restrict__ Bm,
         float* __restrict__ C, int M, int N, int K, int lda,
         const float* __restrict__ bias, int do_relu) {
    __shared__ unsigned As[32][132];
    __shared__ unsigned Bs[32][132];
    int tid = threadIdx.x;
    int bm = blockIdx.y * 128, bn = blockIdx.x * 128;
    int warp = tid >> 5, lane = tid & 31;
    int wm = warp & 3, wn = warp >> 2;           // 4x2 warp grid
    int g = lane >> 2, t4 = lane & 3;

    float c[2][8][4];
    #pragma unroll
    for (int i = 0; i < 2; i++)
        #pragma unroll
        for (int j = 0; j < 8; j++)
            #pragma unroll
            for (int r = 0; r < 4; r++) c[i][j][r] = 0.f;

    for (int k0 = 0; k0 < K; k0 += 32) {
        // ---- load A tile -> As[k][m] (tf32) ----
        if (MODE == 0) {
            int m = tid >> 1, half = tid & 1;
            int gm = bm + m;
            #pragma unroll
            for (int i = 0; i < 4; i++) {
                int kof = half * 16 + i * 4;
                float4 v = make_float4(0.f, 0.f, 0.f, 0.f);
                if (gm < M) v = *(const float4*)(A + (size_t)gm * lda + k0 + kof);
                As[kof + 0][m] = f2tf(v.x);
                As[kof + 1][m] = f2tf(v.y);
                As[kof + 2][m] = f2tf(v.z);
                As[kof + 3][m] = f2tf(v.w);
            }
        } else {
            #pragma unroll
            for (int j = 0; j < 16; j++) {
                int l = tid * 16 + j;
                int m = l >> 5, kk = l & 31;
                int gm = bm + m, gk = k0 + kk;
                float v = 0.f;
                if (MODE == 1) {
                    int b = gm >> 12, s = gm & 4095;
                    int od = s >> 8, oh = (s >> 4) & 15, ow = s & 15;
                    int cc = gk >> 6, r = gk & 63;
                    int kd = r >> 4, kh = (r >> 2) & 3, kw = r & 3;
                    int id = od * 2 - 1 + kd, ih = oh * 2 - 1 + kh, iw = ow * 2 - 1 + kw;
                    if ((unsigned)id <= 31u && (unsigned)ih <= 31u && (unsigned)iw <= 31u)
                        v = A[(((size_t)((b << 8) + cc)) << 15) + (id << 10) + (ih << 5) + iw];
                } else {
                    int b = gm >> 12, s = gm & 4095;
                    int od = s >> 8, oh = (s >> 4) & 15, ow = s & 15;
                    int cc = gk / 27, r = gk - cc * 27;
                    int kd = r / 9; r -= kd * 9;
                    int kh = r / 3; int kw = r - kh * 3;
                    int id = od - 1 + kd, ih = oh - 1 + kh, iw = ow - 1 + kw;
                    if ((unsigned)id <= 15u && (unsigned)ih <= 15u && (unsigned)iw <= 15u)
                        v = A[((size_t)((b << 12) + (id << 8) + (ih << 4) + iw)) * 512 + cc];
                }
                As[kk][m] = f2tf(v);
            }
        }
        // ---- load B tile -> Bs[k][n] (tf32) ----
        {
            int kk = tid >> 3, quad = tid & 7;
            const float* brow = Bm + (size_t)(k0 + kk) * N + bn;
            #pragma unroll
            for (int i = 0; i < 4; i++) {
                int n = quad * 16 + i * 4;
                float4 v = make_float4(0.f, 0.f, 0.f, 0.f);
                if (bn + n < N) v = *(const float4*)(brow + n);
                uint4 u;
                u.x = f2tf(v.x); u.y = f2tf(v.y); u.z = f2tf(v.z); u.w = f2tf(v.w);
                *(uint4*)&Bs[kk][n] = u;
            }
        }
        __syncthreads();
        // ---- compute ----
        #pragma unroll
        for (int ks = 0; ks < 4; ks++) {
            int kb = ks * 8;
            unsigned a[2][4], b[8][2];
            #pragma unroll
            for (int mt = 0; mt < 2; mt++) {
                int m0 = wm * 32 + mt * 16;
                a[mt][0] = As[kb + t4][m0 + g];
                a[mt][1] = As[kb + t4][m0 + g + 8];
                a[mt][2] = As[kb + t4 + 4][m0 + g];
                a[mt][3] = As[kb + t4 + 4][m0 + g + 8];
            }
            #pragma unroll
            for (int nt = 0; nt < 8; nt++) {
                int n0 = wn * 64 + nt * 8;
                b[nt][0] = Bs[kb + t4][n0 + g];
                b[nt][1] = Bs[kb + t4 + 4][n0 + g];
            }
            #pragma unroll
            for (int mt = 0; mt < 2; mt++)
                #pragma unroll
                for (int nt = 0; nt < 8; nt++) {
                    asm volatile(
                        "mma.sync.aligned.m16n8k8.row.col.f32.tf32.tf32.f32 "
                        "{%0,%1,%2,%3}, {%4,%5,%6,%7}, {%8,%9}, {%0,%1,%2,%3};"
                        : "+f"(c[mt][nt][0]), "+f"(c[mt][nt][1]),
                          "+f"(c[mt][nt][2]), "+f"(c[mt][nt][3])
                        : "r"(a[mt][0]), "r"(a[mt][1]), "r"(a[mt][2]), "r"(a[mt][3]),
                          "r"(b[nt][0]), "r"(b[nt][1]));
                }
        }
        __syncthreads();
    }
    // ---- store ----
    #pragma unroll
    for (int mt = 0; mt < 2; mt++) {
        #pragma unroll
        for (int nt = 0; nt < 8; nt++) {
            int gn0 = bn + wn * 64 + nt * 8 + 2 * t4;
            #pragma unroll
            for (int r = 0; r < 4; r++) {
                int gm = bm + wm * 32 + mt * 16 + g + (r >> 1) * 8;
                int gn = gn0 + (r & 1);
                if (gm < M && gn < N) {
                    float v = c[mt][nt][r];
                    if (bias) v += bias[gn];
                    if (do_relu) v = fmaxf(v, 0.f);
                    C[(size_t)gm * N + gn] = v;
                }
            }
        }
    }
}

// ------------------------- node feature gather -------------------------
__global__ void node_gather(const float* __restrict__ pos) {
    int r = blockIdx.x;
    int b = r / NNODES, n = r - b * NNODES;
    float p0 = pos[n * 3], p1 = pos[n * 3 + 1], p2 = pos[n * 3 + 2];
    int i0 = (int)(p0 * 16.f - 1.f);
    int i1 = (int)(p1 * 16.f - 1.f);
    int i2 = (int)(p2 * 16.f - 1.f);
    int vox = (i0 << 8) + (i1 << 4) + i2;
    const float* src = g_f2 + ((size_t)((b << 12) + vox)) * 512;
    float* drow = g_node + (size_t)r * K1P;
    for (int c = threadIdx.x; c < K1P; c += blockDim.x) {
        float v;
        if (c < 3)        v = (c == 0) ? p0 : ((c == 1) ? p1 : p2);
        else if (c < 515) v = src[c - 3];
        else              v = 0.f;
        drow[c] = v;
    }
}

// ------------------------- gated edge messages (kqvs layout) -------------------------
// row layout: [k | q | v | h] each F wide, stride = 4F
__global__ void edge_kernel(float* __restrict__ base, int stride, int F,
                            const int* __restrict__ ei) {
    int j = blockIdx.x;                 // 0 .. 2*NEDGES-1
    int b = (j >= NEDGES) ? 1 : 0;
    int e = j - b * NEDGES;
    int src = ei[e] + b * NNODES;
    int dst = ei[NEDGES + e] + b * NNODES;
    int c = threadIdx.x;
    const float* drow = base + (size_t)dst * stride;
    const float* srow = base + (size_t)src * stride;
    float kv = drow[c];
    float qv = srow[F + c];
    float vv = srow[2 * F + c];
    float gt = 1.f / (1.f + expf(-(kv + qv)));
    atomicAdd(base + (size_t)dst * stride + 3 * F + c, gt * vv);
}

__global__ void relu_strided(float* __restrict__ p, int rows, int stride, int off, int F) {
    int i = blockIdx.x * blockDim.x + threadIdx.x;
    if (i >= rows * F) return;
    int r = i / F, c = i - r * F;
    float* q = p + (size_t)r * stride + off + c;
    *q = fmaxf(*q, 0.f);
}

// ------------------------- final tiny layer (N=3) -------------------------
__global__ void mlp2_kernel(const float* __restrict__ w, const float* __restrict__ bb,
                            float* __restrict__ out) {
    int r = blockIdx.x * blockDim.x + threadIdx.x;
    if (r >= NTOT) return;
    const float* row = g_h3 + (size_t)r * 64;
    float a0 = bb[0], a1 = bb[1], a2 = bb[2];
    #pragma unroll
    for (int k = 0; k < 64; k++) {
        float xv = row[k];
        a0 = fmaf(xv, __ldg(&w[k * 3 + 0]), a0);
        a1 = fmaf(xv, __ldg(&w[k * 3 + 1]), a1);
        a2 = fmaf(xv, __ldg(&w[k * 3 + 2]), a2);
    }
    out[r * 3 + 0] = fmaxf(a0, 0.f);
    out[r * 3 + 1] = fmaxf(a1, 0.f);
    out[r * 3 + 2] = fmaxf(a2, 0.f);
}

// ------------------------- launcher -------------------------
extern "C" void kernel_launch(void* const* d_in, const int* in_sizes, int n_in,
                              void* d_out, int out_size) {
    const float* x   = (const float*)d_in[0];
    const float* pos = (const float*)d_in[1];
    const float* w0  = (const float*)d_in[2];
    const float* g0  = (const float*)d_in[3];
    const float* b0  = (const float*)d_in[4];
    const float* w1  = (const float*)d_in[5];
    const float* g1  = (const float*)d_in[6];
    const float* b1  = (const float*)d_in[7];
    const float* w2  = (const float*)d_in[8];
    const float* g2  = (const float*)d_in[9];
    const float* b2  = (const float*)d_in[10];
    const float* gk1 = (const float*)d_in[11];
    const float* gq1 = (const float*)d_in[12];
    const float* gv1 = (const float*)d_in[13];
    const float* gs1 = (const float*)d_in[14];
    const float* gb1 = (const float*)d_in[15];
    const float* gk2 = (const float*)d_in[16];
    const float* gq2 = (const float*)d_in[17];
    const float* gv2 = (const float*)d_in[18];
    const float* gs2 = (const float*)d_in[19];
    const float* gb2 = (const float*)d_in[20];
    const float* m1w = (const float*)d_in[21];
    const float* m1b = (const float*)d_in[22];
    const float* m2w = (const float*)d_in[23];
    const float* m2b = (const float*)d_in[24];
    const int*   ei  = (const int*)d_in[25];
    float* out = (float*)d_out;

    float *p_f0, *p_f1, *p_f2, *p_w1t, *p_w2t, *p_node;
    float *p_wcat1, *p_wcat2, *p_bias1, *p_bias2, *p_kqvs1, *p_kqvs2, *p_h3;
    cudaGetSymbolAddress((void**)&p_f0,    g_f0);
    cudaGetSymbolAddress((void**)&p_f1,    g_f1);
    cudaGetSymbolAddress((void**)&p_f2,    g_f2);
    cudaGetSymbolAddress((void**)&p_w1t,   g_w1t);
    cudaGetSymbolAddress((void**)&p_w2t,   g_w2t);
    cudaGetSymbolAddress((void**)&p_node,  g_node);
    cudaGetSymbolAddress((void**)&p_wcat1, g_wcat1);
    cudaGetSymbolAddress((void**)&p_wcat2, g_wcat2);
    cudaGetSymbolAddress((void**)&p_bias1, g_bias1);
    cudaGetSymbolAddress((void**)&p_bias2, g_bias2);
    cudaGetSymbolAddress((void**)&p_kqvs1, g_kqvs1);
    cudaGetSymbolAddress((void**)&p_kqvs2, g_kqvs2);
    cudaGetSymbolAddress((void**)&p_h3,    g_h3);

    // conv0 + bn + relu
    conv0_kernel<<<dim3(128, 256, 2), 256>>>(x, w0);
    bn_stats_bcs<<<256, 256>>>(p_f0, 256, 32768, 2, g0, b0);
    bn_apply_bcs<<<CDIV(16777216, 256), 256>>>(p_f0, 256, 32768, 16777216, 1);

    // weight prep
    transpose_kernel<<<dim3(16384 / 32, 512 / 32), dim3(32, 8)>>>(w1, p_w1t, 512, 16384);
    transpose_kernel<<<dim3(13824 / 32, 512 / 32), dim3(32, 8)>>>(w2, p_w2t, 512, 13824);
    concat_weight<<<CDIV(K1P * 256, 256), 256>>>(gk1, p_wcat1, 515, K1P, 256, 0,   1024);
    concat_weight<<<CDIV(K1P * 256, 256), 256>>>(gq1, p_wcat1, 515, K1P, 256, 256, 1024);
    concat_weight<<<CDIV(K1P * 256, 256), 256>>>(gv1, p_wcat1, 515, K1P, 256, 512, 1024);
    concat_weight<<<CDIV(K1P * 256, 256), 256>>>(gs1, p_wcat1, 515, K1P, 256, 768, 1024);
    concat_weight<<<CDIV(256 * 128, 256), 256>>>(gk2, p_wcat2, 256, 256, 128, 0,   512);
    concat_weight<<<CDIV(256 * 128, 256), 256>>>(gq2, p_wcat2, 256, 256, 128, 128, 512);
    concat_weight<<<CDIV(256 * 128, 256), 256>>>(gv2, p_wcat2, 256, 256, 128, 256, 512);
    concat_weight<<<CDIV(256 * 128, 256), 256>>>(gs2, p_wcat2, 256, 256, 128, 384, 512);
    build_bias<<<4, 256>>>(gb1, p_bias1, 768, 256, 1024);
    build_bias<<<2, 256>>>(gb2, p_bias2, 384, 128, 512);

    // conv1 (implicit GEMM, tf32) + bn + relu
    mma_gemm<1><<<dim3(4, 64), 256>>>(p_f0, p_w1t, p_f1, 8192, 512, 16384, 0, nullptr, 0);
    bn_stats_rc<<<512, 256>>>(p_f1, 512, 8192, g1, b1);
    bn_apply_rc<<<CDIV(4194304, 256), 256>>>(p_f1, 512, 4194304, 1);

    // conv2 (implicit GEMM, tf32) + bn
    mma_gemm<2><<<dim3(4, 64), 256>>>(p_f1, p_w2t, p_f2, 8192, 512, 13824, 0, nullptr, 0);
    bn_stats_rc<<<512, 256>>>(p_f2, 512, 8192, g2, b2);
    bn_apply_rc<<<CDIV(4194304, 256), 256>>>(p_f2, 512, 4194304, 0);

    // node features
    node_gather<<<NTOT, 128>>>(pos);

    // GNN layer 1: fused kqvs GEMM + edges + relu(h)
    mma_gemm<0><<<dim3(8, CDIV(NTOT, 128)), 256>>>(p_node, p_wcat1, p_kqvs1,
                                                   NTOT, 1024, K1P, K1P, p_bias1, 0);
    edge_kernel<<<2 * NEDGES, 256>>>(p_kqvs1, 1024, 256, ei);
    relu_strided<<<CDIV(NTOT * 256, 256), 256>>>(p_kqvs1, NTOT, 1024, 768, 256);

    // GNN layer 2
    mma_gemm<0><<<dim3(4, CDIV(NTOT, 128)), 256>>>(p_kqvs1 + 768, p_wcat2, p_kqvs2,
                                                   NTOT, 512, 256, 1024, p_bias2, 0);
    edge_kernel<<<2 * NEDGES, 128>>>(p_kqvs2, 512, 128, ei);
    relu_strided<<<CDIV(NTOT * 128, 256), 256>>>(p_kqvs2, NTOT, 512, 384, 128);

    // MLP head
    mma_gemm<0><<<dim3(1, CDIV(NTOT, 128)), 256>>>(p_kqvs2 + 384, m1w, p_h3,
                                                   NTOT, 64, 128, 512, m1b, 1);
    mlp2_kernel<<<CDIV(NTOT, 256), 256>>>(m2w, m2b, out);
}

// round 5
// speedup vs baseline: 3.0318x; 1.4282x over previous
#include <cuda_runtime.h>
#include <math.h>

#define CDIV(a,b) (((a)+(b)-1)/(b))

namespace {
constexpr int NNODES = 50000;
constexpr int NEDGES = 300000;
constexpr int NTOT   = 100000;
constexpr int SMEM_BYTES = (2 * 128 * 36 + 2 * 32 * 136) * 4;   // 71680
}

// ------------------------- static device scratch -------------------------
__device__ float    g_f0 [16777216];   // (2,256,32^3) conv0 out fp32
__device__ unsigned g_f0t[16777216];   // tf32 bits after bn+relu
__device__ float    g_f1 [4194304];    // (2,16^3,512) conv1 out fp32
__device__ unsigned g_f1t[4194304];
__device__ float    g_f2 [4194304];    // conv2 out fp32
__device__ unsigned g_f2t[4194304];
__device__ unsigned g_w1t[8388608];    // w1^T (16384,512) tf32
__device__ unsigned g_w2t[7077888];    // w2^T (13824,512) tf32
__device__ unsigned g_wfeat1t[524288]; // (512,1024) tf32 = rows 3..514 of [Wk|Wq|Wv|Ws]
__device__ float    g_wpos1[3072];     // (3,1024) fp32 pos rows
__device__ float    g_bias1[1024];
__device__ unsigned g_wcat2t[131072];  // (256,512) tf32
__device__ float    g_bias2[512];
__device__ unsigned g_m1wt[8192];      // (128,64) tf32
__device__ float    g_voxout[8388608]; // (8192,1024)
__device__ float    g_kqvs1[102400000];// (100000,1024)
__device__ unsigned g_h1t[25600000];   // (100000,256) tf32
__device__ float    g_kqvs2[51200000]; // (100000,512)
__device__ unsigned g_h2t[12800000];   // (100000,128) tf32
__device__ float    g_h3[6400000];     // (100000,64)
__device__ float    g_scale[512];
__device__ float    g_shift[512];

__device__ __forceinline__ unsigned f2tf(float x) {
    unsigned r;
    asm("cvt.rna.tf32.f32 %0, %1;" : "=r"(r) : "f"(x));
    return r;
}

__device__ __forceinline__ void cpa16(void* dst, const void* src, bool pred) {
    unsigned d = (unsigned)__cvta_generic_to_shared(dst);
    int sz = pred ? 16 : 0;
    asm volatile("cp.async.cg.shared.global [%0], [%1], 16, %2;\n" :: "r"(d), "l"(src), "r"(sz));
}
__device__ __forceinline__ void cpa4(void* dst, const void* src, bool pred) {
    unsigned d = (unsigned)__cvta_generic_to_shared(dst);
    int sz = pred ? 4 : 0;
    asm volatile("cp.async.ca.shared.global [%0], [%1], 4, %2;\n" :: "r"(d), "l"(src), "r"(sz));
}

// ------------------------- conv0: direct 3x3x3, C_in=4 (fp32) -------------------------
__global__ void conv0_kernel(const float* __restrict__ x, const float* __restrict__ w0) {
    __shared__ float ws[108];
    int co = blockIdx.y, b = blockIdx.z;
    if (threadIdx.x < 108) ws[threadIdx.x] = w0[co * 108 + threadIdx.x];
    __syncthreads();
    int s = blockIdx.x * 256 + threadIdx.x;
    int z = s >> 10, y = (s >> 5) & 31, xx = s & 31;
    float acc = 0.f;
    #pragma unroll
    for (int ci = 0; ci < 4; ci++) {
        const float* xb = x + ((size_t)(b * 4 + ci) << 15);
        const float* wc = ws + ci * 27;
        #pragma unroll
        for (int kd = 0; kd < 3; kd++) {
            int id = z + kd - 1;
            if ((unsigned)id > 31u) continue;
            #pragma unroll
            for (int kh = 0; kh < 3; kh++) {
                int ih = y + kh - 1;
                if ((unsigned)ih > 31u) continue;
                #pragma unroll
                for (int kw = 0; kw < 3; kw++) {
                    int iw = xx + kw - 1;
                    if ((unsigned)iw > 31u) continue;
                    acc = fmaf(xb[(id << 10) + (ih << 5) + iw], wc[kd * 9 + kh * 3 + kw], acc);
                }
            }
        }
    }
    g_f0[(((size_t)((b << 8) + co)) << 15) + s] = acc;
}

// ------------------------- batchnorm -------------------------
__global__ void bn_stats_bcs(const float* __restrict__ x, int C, int S, int Bn,
                             const float* __restrict__ gm, const float* __restrict__ bt) {
    int c = blockIdx.x;
    int total = Bn * S;
    double s1 = 0.0, s2 = 0.0;
    for (int e = threadIdx.x; e < total; e += blockDim.x) {
        int b = e / S, ss = e - b * S;
        float v = x[((size_t)(b * C + c)) * S + ss];
        s1 += v; s2 += (double)v * v;
    }
    __shared__ double r1[256], r2[256];
    int tid = threadIdx.x;
    r1[tid] = s1; r2[tid] = s2; __syncthreads();
    for (int o = 128; o; o >>= 1) {
        if (tid < o) { r1[tid] += r1[tid + o]; r2[tid] += r2[tid + o]; }
        __syncthreads();
    }
    if (tid == 0) {
        double mean = r1[0] / total;
        double var  = r2[0] / total - mean * mean;
        float sc = gm[c] * rsqrtf((float)var + 1e-5f);
        g_scale[c] = sc;
        g_shift[c] = bt[c] - (float)mean * sc;
    }
}

__global__ void bn_stats_rc(const float* __restrict__ x, int C, int rows,
                            const float* __restrict__ gm, const float* __restrict__ bt) {
    int c = blockIdx.x;
    double s1 = 0.0, s2 = 0.0;
    for (int r = threadIdx.x; r < rows; r += blockDim.x) {
        float v = x[(size_t)r * C + c];
        s1 += v; s2 += (double)v * v;
    }
    __shared__ double r1[256], r2[256];
    int tid = threadIdx.x;
    r1[tid] = s1; r2[tid] = s2; __syncthreads();
    for (int o = 128; o; o >>= 1) {
        if (tid < o) { r1[tid] += r1[tid + o]; r2[tid] += r2[tid + o]; }
        __syncthreads();
    }
    if (tid == 0) {
        double mean = r1[0] / rows;
        double var  = r2[0] / rows - mean * mean;
        float sc = gm[c] * rsqrtf((float)var + 1e-5f);
        g_scale[c] = sc;
        g_shift[c] = bt[c] - (float)mean * sc;
    }
}

// bn-apply writing tf32 bits (layout (b,c,s))
__global__ void bn_apply_bcs_t(const float* __restrict__ x, unsigned* __restrict__ o,
                               int C, int S, int n, int do_relu) {
    int i = blockIdx.x * blockDim.x + threadIdx.x;
    if (i >= n) return;
    int c = (i / S) % C;
    float v = x[i] * g_scale[c] + g_shift[c];
    if (do_relu) v = fmaxf(v, 0.f);
    o[i] = f2tf(v);
}

// bn-apply writing tf32 bits (layout (rows, C))
__global__ void bn_apply_rc_t(const float* __restrict__ x, unsigned* __restrict__ o,
                              int C, int n, int do_relu) {
    int i = blockIdx.x * blockDim.x + threadIdx.x;
    if (i >= n) return;
    int c = i % C;
    float v = x[i] * g_scale[c] + g_shift[c];
    if (do_relu) v = fmaxf(v, 0.f);
    o[i] = f2tf(v);
}

// ------------------------- weight prep -------------------------
__global__ void transpose_t(const float* __restrict__ src, unsigned* __restrict__ dst,
                            int R, int Ccols) {
    __shared__ float tile[32][33];
    int c0 = blockIdx.x * 32, r0 = blockIdx.y * 32;
    int x = threadIdx.x, y = threadIdx.y;
    for (int i = y; i < 32; i += 8) {
        int r = r0 + i, c = c0 + x;
        tile[i][x] = (r < R && c < Ccols) ? src[(size_t)r * Ccols + c] : 0.f;
    }
    __syncthreads();
    for (int i = y; i < 32; i += 8) {
        int c = c0 + i, r = r0 + x;
        if (c < Ccols && r < R) dst[(size_t)c * R + r] = f2tf(tile[x][i]);
    }
}

// dst[k*Nout + off + f] = tf32(src[(k+rowOff)*F + f]) for k < Kin else 0
__global__ void concat_w_t(const float* __restrict__ src, unsigned* __restrict__ dst,
                           int rowOff, int Kin, int Kpad, int F, int off, int Nout) {
    int i = blockIdx.x * blockDim.x + threadIdx.x;
    if (i >= Kpad * F) return;
    int k = i / F, f = i - k * F;
    float v = (k < Kin) ? src[(size_t)(k + rowOff) * F + f] : 0.f;
    dst[(size_t)k * Nout + off + f] = f2tf(v);
}

// fp32 row copy (pos weight rows)
__global__ void copy_rows(const float* __restrict__ src, float* __restrict__ dst,
                          int rows, int F, int off, int Nout) {
    int i = blockIdx.x * blockDim.x + threadIdx.x;
    if (i >= rows * F) return;
    int k = i / F, f = i - k * F;
    dst[(size_t)k * Nout + off + f] = src[(size_t)k * F + f];
}

__global__ void build_bias(const float* __restrict__ src, float* __restrict__ dst,
                           int off, int F, int Nout) {
    int i = blockIdx.x * blockDim.x + threadIdx.x;
    if (i >= Nout) return;
    dst[i] = (i >= off && i < off + F) ? src[i - off] : 0.f;
}

// ------------------------- tf32 tensor-core GEMM (cp.async 2-stage) -------------------------
// C[M,N] = A[M,K] @ B[K,N] (+bias)(+relu). BM=128, BN=128, BK=32, 256 threads.
// A/B hold pre-converted tf32 bits.
// MODE 0: A row-major, leading dim lda.  MODE 1/2: implicit im2col (conv1/conv2).
#define ASD(s,m,k) sA[(s) * 4608 + (m) * 36 + (k)]
#define BSD(s,k,n) sB[(s) * 4352 + (k) * 136 + (n)]
template<int MODE>
__global__ void __launch_bounds__(256)
mma_gemm(const unsigned* __restrict__ A, const unsigned* __restrict__ Bm,
         float* __restrict__ C, int M, int N, int K, int lda,
         const float* __restrict__ bias, int do_relu) {
    extern __shared__ unsigned sm_raw[];
    unsigned* sA = sm_raw;            // 2 * 128 * 36
    unsigned* sB = sm_raw + 9216;     // 2 * 32 * 136
    int tid = threadIdx.x;
    int bm = blockIdx.y * 128, bn = blockIdx.x * 128;
    int warp = tid >> 5, lane = tid & 31;
    int wm = warp & 3, wn = warp >> 2;
    int g = lane >> 2, t4 = lane & 3;

    float c[2][8][4];
    #pragma unroll
    for (int i = 0; i < 2; i++)
        #pragma unroll
        for (int j = 0; j < 8; j++)
            #pragma unroll
            for (int r = 0; r < 4; r++) c[i][j][r] = 0.f;

    int ntiles = K >> 5;

    auto load_tile = [&](int s, int k0) {
        // ---- A ----
        if (MODE == 0) {
            int m = tid >> 1, half = tid & 1;
            int gm = bm + m;
            bool ok = gm < M;
            const unsigned* arow = A + (size_t)gm * lda + k0;
            #pragma unroll
            for (int i = 0; i < 2; i++) {
                int kof = half * 16 + i * 8;
                cpa16(&ASD(s, m, kof),     ok ? (arow + kof)     : A, ok);
                cpa16(&ASD(s, m, kof + 4), ok ? (arow + kof + 4) : A, ok);
            }
        } else {
            #pragma unroll
            for (int j = 0; j < 16; j++) {
                int l = tid * 16 + j;
                int m = l >> 5, kk = l & 31;
                int gm = bm + m, gk = k0 + kk;
                size_t idx = 0; bool ok = false;
                if (MODE == 1) {
                    int b = gm >> 12, ss = gm & 4095;
                    int od = ss >> 8, oh = (ss >> 4) & 15, ow = ss & 15;
                    int cc = gk >> 6, r = gk & 63;
                    int kd = r >> 4, kh = (r >> 2) & 3, kw = r & 3;
                    int id = od * 2 - 1 + kd, ih = oh * 2 - 1 + kh, iw = ow * 2 - 1 + kw;
                    ok = (unsigned)id <= 31u && (unsigned)ih <= 31u && (unsigned)iw <= 31u;
                    idx = (((size_t)((b << 8) + cc)) << 15) + (id << 10) + (ih << 5) + iw;
                } else {
                    int b = gm >> 12, ss = gm & 4095;
                    int od = ss >> 8, oh = (ss >> 4) & 15, ow = ss & 15;
                    int cc = gk / 27, r = gk - cc * 27;
                    int kd = r / 9; r -= kd * 9;
                    int kh = r / 3; int kw = r - kh * 3;
                    int id = od - 1 + kd, ih = oh - 1 + kh, iw = ow - 1 + kw;
                    ok = (unsigned)id <= 15u && (unsigned)ih <= 15u && (unsigned)iw <= 15u;
                    idx = ((size_t)((b << 12) + (id << 8) + (ih << 4) + iw)) * 512 + cc;
                }
                cpa4(&ASD(s, m, kk), ok ? (A + idx) : A, ok);
            }
        }
        // ---- B ----
        {
            int kk = tid >> 3, quad = tid & 7;
            const unsigned* brow = Bm + (size_t)(k0 + kk) * N + bn;
            #pragma unroll
            for (int i = 0; i < 4; i++) {
                int n = quad * 16 + i * 4;
                bool ok = (bn + n) < N;
                cpa16(&BSD(s, kk, n), ok ? (brow + n) : Bm, ok);
            }
        }
        asm volatile("cp.async.commit_group;\n");
    };

    load_tile(0, 0);
    for (int t = 0; t < ntiles; t++) {
        int s = t & 1;
        if (t + 1 < ntiles) {
            load_tile(s ^ 1, (t + 1) << 5);
            asm volatile("cp.async.wait_group 1;\n");
        } else {
            asm volatile("cp.async.wait_group 0;\n");
        }
        __syncthreads();
        #pragma unroll
        for (int ks = 0; ks < 4; ks++) {
            int kb = ks * 8;
            unsigned a[2][4], b[8][2];
            #pragma unroll
            for (int mt = 0; mt < 2; mt++) {
                int m0 = wm * 32 + mt * 16;
                a[mt][0] = ASD(s, m0 + g,     kb + t4);
                a[mt][1] = ASD(s, m0 + g + 8, kb + t4);
                a[mt][2] = ASD(s, m0 + g,     kb + t4 + 4);
                a[mt][3] = ASD(s, m0 + g + 8, kb + t4 + 4);
            }
            #pragma unroll
            for (int nt = 0; nt < 8; nt++) {
                int n0 = wn * 64 + nt * 8;
                b[nt][0] = BSD(s, kb + t4,     n0 + g);
                b[nt][1] = BSD(s, kb + t4 + 4, n0 + g);
            }
            #pragma unroll
            for (int mt = 0; mt < 2; mt++)
                #pragma unroll
                for (int nt = 0; nt < 8; nt++) {
                    asm volatile(
                        "mma.sync.aligned.m16n8k8.row.col.f32.tf32.tf32.f32 "
                        "{%0,%1,%2,%3}, {%4,%5,%6,%7}, {%8,%9}, {%0,%1,%2,%3};"
                        : "+f"(c[mt][nt][0]), "+f"(c[mt][nt][1]),
                          "+f"(c[mt][nt][2]), "+f"(c[mt][nt][3])
                        : "r"(a[mt][0]), "r"(a[mt][1]), "r"(a[mt][2]), "r"(a[mt][3]),
                          "r"(b[nt][0]), "r"(b[nt][1]));
                }
        }
        __syncthreads();
    }
    #pragma unroll
    for (int mt = 0; mt < 2; mt++) {
        #pragma unroll
        for (int nt = 0; nt < 8; nt++) {
            int gn0 = bn + wn * 64 + nt * 8 + 2 * t4;
            #pragma unroll
            for (int r = 0; r < 4; r++) {
                int gm = bm + wm * 32 + mt * 16 + g + (r >> 1) * 8;
                int gn = gn0 + (r & 1);
                if (gm < M && gn < N) {
                    float v = c[mt][nt][r];
                    if (bias) v += bias[gn];
                    if (do_relu) v = fmaxf(v, 0.f);
                    C[(size_t)gm * N + gn] = v;
                }
            }
        }
    }
}

// ------------------------- per-node scatter: kqvs1 = voxout[vox] + pos*Wpos + bias ---------
__global__ void knode_kernel(const float* __restrict__ pos) {
    int r = blockIdx.x;
    int b = r / NNODES, n = r - b * NNODES;
    float p0 = pos[n * 3], p1 = pos[n * 3 + 1], p2 = pos[n * 3 + 2];
    int i0 = (int)(p0 * 16.f - 1.f);
    int i1 = (int)(p1 * 16.f - 1.f);
    int i2 = (int)(p2 * 16.f - 1.f);
    int vox = (i0 << 8) + (i1 << 4) + i2;
    const float4* vrow = (const float4*)(g_voxout + ((size_t)((b << 12) + vox)) * 1024);
    const float4* wr0  = (const float4*)(g_wpos1);
    const float4* wr1  = (const float4*)(g_wpos1 + 1024);
    const float4* wr2  = (const float4*)(g_wpos1 + 2048);
    const float4* br   = (const float4*)(g_bias1);
    float4* drow = (float4*)(g_kqvs1 + (size_t)r * 1024);
    int c = threadIdx.x;                 // 0..255 -> 4 floats each
    float4 v = vrow[c], w0 = wr0[c], w1 = wr1[c], w2 = wr2[c], bb = br[c];
    float4 o;
    o.x = v.x + p0 * w0.x + p1 * w1.x + p2 * w2.x + bb.x;
    o.y = v.y + p0 * w0.y + p1 * w1.y + p2 * w2.y + bb.y;
    o.z = v.z + p0 * w0.z + p1 * w1.z + p2 * w2.z + bb.z;
    o.w = v.w + p0 * w0.w + p1 * w1.w + p2 * w2.w + bb.w;
    drow[c] = o;
}

// ------------------------- gated edge messages (float4) -------------------------
// row layout: [k | q | v | h] each F wide, stride = 4F.  EPB edges per block.
template<int F, int EPB>
__global__ void edge_kernel4(float* __restrict__ base, const int* __restrict__ ei) {
    constexpr int TPE = F / 4;           // threads per edge
    int tid = threadIdx.x;
    int j = blockIdx.x * EPB + tid / TPE;
    int b = (j >= NEDGES) ? 1 : 0;
    int e = j - b * NEDGES;
    int src = __ldg(ei + e) + b * NNODES;
    int dst = __ldg(ei + NEDGES + e) + b * NNODES;
    int c = (tid % TPE) * 4;
    const float* drow = base + (size_t)dst * (4 * F);
    const float* srow = base + (size_t)src * (4 * F);
    float4 kv = *(const float4*)(drow + c);
    float4 qv = *(const float4*)(srow + F + c);
    float4 vv = *(const float4*)(srow + 2 * F + c);
    float* hp = base + (size_t)dst * (4 * F) + 3 * F + c;
    atomicAdd(hp + 0, vv.x / (1.f + __expf(-(kv.x + qv.x))));
    atomicAdd(hp + 1, vv.y / (1.f + __expf(-(kv.y + qv.y))));
    atomicAdd(hp + 2, vv.z / (1.f + __expf(-(kv.z + qv.z))));
    atomicAdd(hp + 3, vv.w / (1.f + __expf(-(kv.w + qv.w))));
}

// relu on strided segment, packed to contiguous tf32
__global__ void relu_pack(const float* __restrict__ src, unsigned* __restrict__ dst,
                          int rows, int stride, int off, int F) {
    int i = blockIdx.x * blockDim.x + threadIdx.x;
    if (i >= rows * F) return;
    int r = i / F, c = i - r * F;
    float v = fmaxf(src[(size_t)r * stride + off + c], 0.f);
    dst[(size_t)r * F + c] = f2tf(v);
}

// ------------------------- final tiny layer (N=3) -------------------------
__global__ void mlp2_kernel(const float* __restrict__ w, const float* __restrict__ bb,
                            float* __restrict__ out) {
    int r = blockIdx.x * blockDim.x + threadIdx.x;
    if (r >= NTOT) return;
    const float* row = g_h3 + (size_t)r * 64;
    float a0 = bb[0], a1 = bb[1], a2 = bb[2];
    #pragma unroll
    for (int k = 0; k < 64; k++) {
        float xv = row[k];
        a0 = fmaf(xv, __ldg(&w[k * 3 + 0]), a0);
        a1 = fmaf(xv, __ldg(&w[k * 3 + 1]), a1);
        a2 = fmaf(xv, __ldg(&w[k * 3 + 2]), a2);
    }
    out[r * 3 + 0] = fmaxf(a0, 0.f);
    out[r * 3 + 1] = fmaxf(a1, 0.f);
    out[r * 3 + 2] = fmaxf(a2, 0.f);
}

// ------------------------- launcher -------------------------
extern "C" void kernel_launch(void* const* d_in, const int* in_sizes, int n_in,
                              void* d_out, int out_size) {
    const float* x   = (const float*)d_in[0];
    const float* pos = (const float*)d_in[1];
    const float* w0  = (const float*)d_in[2];
    const float* g0  = (const float*)d_in[3];
    const float* b0  = (const float*)d_in[4];
    const float* w1  = (const float*)d_in[5];
    const float* g1  = (const float*)d_in[6];
    const float* b1  = (const float*)d_in[7];
    const float* w2  = (const float*)d_in[8];
    const float* g2  = (const float*)d_in[9];
    const float* b2  = (const float*)d_in[10];
    const float* gk1 = (const float*)d_in[11];
    const float* gq1 = (const float*)d_in[12];
    const float* gv1 = (const float*)d_in[13];
    const float* gs1 = (const float*)d_in[14];
    const float* gb1 = (const float*)d_in[15];
    const float* gk2 = (const float*)d_in[16];
    const float* gq2 = (const float*)d_in[17];
    const float* gv2 = (const float*)d_in[18];
    const float* gs2 = (const float*)d_in[19];
    const float* gb2 = (const float*)d_in[20];
    const float* m1w = (const float*)d_in[21];
    const float* m1b = (const float*)d_in[22];
    const float* m2w = (const float*)d_in[23];
    const float* m2b = (const float*)d_in[24];
    const int*   ei  = (const int*)d_in[25];
    float* out = (float*)d_out;

    float    *p_f0, *p_f1, *p_f2, *p_wpos1, *p_bias1, *p_bias2;
    float    *p_voxout, *p_kqvs1, *p_kqvs2, *p_h3;
    unsigned *p_f0t, *p_f1t, *p_f2t, *p_w1t, *p_w2t, *p_wfeat1t, *p_wcat2t, *p_m1wt;
    unsigned *p_h1t, *p_h2t;
    cudaGetSymbolAddress((void**)&p_f0,      g_f0);
    cudaGetSymbolAddress((void**)&p_f0t,     g_f0t);
    cudaGetSymbolAddress((void**)&p_f1,      g_f1);
    cudaGetSymbolAddress((void**)&p_f1t,     g_f1t);
    cudaGetSymbolAddress((void**)&p_f2,      g_f2);
    cudaGetSymbolAddress((void**)&p_f2t,     g_f2t);
    cudaGetSymbolAddress((void**)&p_w1t,     g_w1t);
    cudaGetSymbolAddress((void**)&p_w2t,     g_w2t);
    cudaGetSymbolAddress((void**)&p_wfeat1t, g_wfeat1t);
    cudaGetSymbolAddress((void**)&p_wpos1,   g_wpos1);
    cudaGetSymbolAddress((void**)&p_bias1,   g_bias1);
    cudaGetSymbolAddress((void**)&p_wcat2t,  g_wcat2t);
    cudaGetSymbolAddress((void**)&p_bias2,   g_bias2);
    cudaGetSymbolAddress((void**)&p_m1wt,    g_m1wt);
    cudaGetSymbolAddress((void**)&p_voxout,  g_voxout);
    cudaGetSymbolAddress((void**)&p_kqvs1,   g_kqvs1);
    cudaGetSymbolAddress((void**)&p_h1t,     g_h1t);
    cudaGetSymbolAddress((void**)&p_kqvs2,   g_kqvs2);
    cudaGetSymbolAddress((void**)&p_h2t,     g_h2t);
    cudaGetSymbolAddress((void**)&p_h3,      g_h3);

    cudaFuncSetAttribute(mma_gemm<0>, cudaFuncAttributeMaxDynamicSharedMemorySize, SMEM_BYTES);
    cudaFuncSetAttribute(mma_gemm<1>, cudaFuncAttributeMaxDynamicSharedMemorySize, SMEM_BYTES);
    cudaFuncSetAttribute(mma_gemm<2>, cudaFuncAttributeMaxDynamicSharedMemorySize, SMEM_BYTES);

    // conv0 + bn + relu -> tf32
    conv0_kernel<<<dim3(128, 256, 2), 256>>>(x, w0);
    bn_stats_bcs<<<256, 256>>>(p_f0, 256, 32768, 2, g0, b0);
    bn_apply_bcs_t<<<CDIV(16777216, 256), 256>>>(p_f0, p_f0t, 256, 32768, 16777216, 1);

    // weight prep
    transpose_t<<<dim3(16384 / 32, 512 / 32), dim3(32, 8)>>>(w1, p_w1t, 512, 16384);
    transpose_t<<<dim3(13824 / 32, 512 / 32), dim3(32, 8)>>>(w2, p_w2t, 512, 13824);
    concat_w_t<<<CDIV(512 * 256, 256), 256>>>(gk1, p_wfeat1t, 3, 512, 512, 256, 0,    1024);
    concat_w_t<<<CDIV(512 * 256, 256), 256>>>(gq1, p_wfeat1t, 3, 512, 512, 256, 256,  1024);
    concat_w_t<<<CDIV(512 * 256, 256), 256>>>(gv1, p_wfeat1t, 3, 512, 512, 256, 512,  1024);
    concat_w_t<<<CDIV(512 * 256, 256), 256>>>(gs1, p_wfeat1t, 3, 512, 512, 256, 768,  1024);
    copy_rows<<<3, 256>>>(gk1, p_wpos1, 3, 256, 0,   1024);
    copy_rows<<<3, 256>>>(gq1, p_wpos1, 3, 256, 256, 1024);
    copy_rows<<<3, 256>>>(gv1, p_wpos1, 3, 256, 512, 1024);
    copy_rows<<<3, 256>>>(gs1, p_wpos1, 3, 256, 768, 1024);
    concat_w_t<<<CDIV(256 * 128, 256), 256>>>(gk2, p_wcat2t, 0, 256, 256, 128, 0,   512);
    concat_w_t<<<CDIV(256 * 128, 256), 256>>>(gq2, p_wcat2t, 0, 256, 256, 128, 128, 512);
    concat_w_t<<<CDIV(256 * 128, 256), 256>>>(gv2, p_wcat2t, 0, 256, 256, 128, 256, 512);
    concat_w_t<<<CDIV(256 * 128, 256), 256>>>(gs2, p_wcat2t, 0, 256, 256, 128, 384, 512);
    concat_w_t<<<CDIV(128 * 64, 256), 256>>>(m1w, p_m1wt, 0, 128, 128, 64, 0, 64);
    build_bias<<<4, 256>>>(gb1, p_bias1, 768, 256, 1024);
    build_bias<<<2, 256>>>(gb2, p_bias2, 384, 128, 512);

    // conv1 + bn + relu -> tf32
    mma_gemm<1><<<dim3(4, 64), 256, SMEM_BYTES>>>(p_f0t, p_w1t, p_f1, 8192, 512, 16384, 0, nullptr, 0);
    bn_stats_rc<<<512, 256>>>(p_f1, 512, 8192, g1, b1);
    bn_apply_rc_t<<<CDIV(4194304, 256), 256>>>(p_f1, p_f1t, 512, 4194304, 1);

    // conv2 + bn -> tf32
    mma_gemm<2><<<dim3(4, 64), 256, SMEM_BYTES>>>(p_f1t, p_w2t, p_f2, 8192, 512, 13824, 0, nullptr, 0);
    bn_stats_rc<<<512, 256>>>(p_f2, 512, 8192, g2, b2);
    bn_apply_rc_t<<<CDIV(4194304, 256), 256>>>(p_f2, p_f2t, 512, 4194304, 0);

    // voxel-level GNN1 GEMM: (8192,512) @ (512,1024)
    mma_gemm<0><<<dim3(8, 64), 256, SMEM_BYTES>>>(p_f2t, p_wfeat1t, p_voxout,
                                                  8192, 1024, 512, 512, nullptr, 0);
    // scatter to nodes + pos contribution + bias
    knode_kernel<<<NTOT, 256>>>(pos);

    // GNN layer 1 edges + relu-pack
    edge_kernel4<256, 4><<<2 * NEDGES / 4, 256>>>(p_kqvs1, ei);
    relu_pack<<<CDIV(NTOT * 256, 256), 256>>>(p_kqvs1, p_h1t, NTOT, 1024, 768, 256);

    // GNN layer 2
    mma_gemm<0><<<dim3(4, CDIV(NTOT, 128)), 256, SMEM_BYTES>>>(p_h1t, p_wcat2t, p_kqvs2,
                                                               NTOT, 512, 256, 256, p_bias2, 0);
    edge_kernel4<128, 8><<<2 * NEDGES / 8, 256>>>(p_kqvs2, ei);
    relu_pack<<<CDIV(NTOT * 128, 256), 256>>>(p_kqvs2, p_h2t, NTOT, 512, 384, 128);

    // MLP head
    mma_gemm<0><<<dim3(1, CDIV(NTOT, 128)), 256, SMEM_BYTES>>>(p_h2t, p_m1wt, p_h3,
                                                               NTOT, 64, 128, 128, m1b, 1);
    mlp2_kernel<<<CDIV(NTOT, 256), 256>>>(m2w, m2b, out);
}

// round 6
// speedup vs baseline: 3.2024x; 1.0563x over previous
#include <cuda_runtime.h>
#include <math.h>

#define CDIV(a,b) (((a)+(b)-1)/(b))

namespace {
constexpr int NNODES = 50000;
constexpr int NEDGES = 300000;
constexpr int NTOT   = 100000;
constexpr int NE2    = 2 * NEDGES;      // 600000
constexpr int SCAN_B = 98;              // CDIV(NTOT, 1024)
constexpr int SMEM_BYTES = (2 * 128 * 36 + 2 * 32 * 136) * 4;   // 71680
}

// ------------------------- static device scratch -------------------------
__device__ float    g_f0 [16777216];   // (2,256,32^3) conv0 out fp32
__device__ unsigned g_f0t[16777216];   // tf32 bits after bn+relu
__device__ float    g_f1 [4194304];    // (2,16^3,512) conv1 out fp32
__device__ unsigned g_f1t[4194304];
__device__ float    g_f2 [4194304];    // conv2 out fp32
__device__ unsigned g_f2t[4194304];
__device__ unsigned g_w1t[8388608];    // w1^T (16384,512) tf32
__device__ unsigned g_w2t[7077888];    // w2^T (13824,512) tf32
__device__ unsigned g_wfeat1t[524288]; // (512,1024) tf32 = rows 3..514 of [Wk|Wq|Wv|Ws]
__device__ float    g_wpos1[3072];     // (3,1024) fp32 pos rows
__device__ float    g_bias1[1024];
__device__ unsigned g_wcat2t[131072];  // (256,512) tf32
__device__ float    g_bias2[512];
__device__ unsigned g_m1wt[8192];      // (128,64) tf32
__device__ float    g_voxout[8388608]; // (8192,1024)
__device__ float    g_kqvs1[102400000];// (100000,1024)
__device__ unsigned g_h1t[25600000];   // (100000,256) tf32
__device__ float    g_kqvs2[51200000]; // (100000,512)
__device__ unsigned g_h2t[12800000];   // (100000,128) tf32
__device__ float    g_h3[6400000];     // (100000,64)
__device__ float    g_scale[512];
__device__ float    g_shift[512];
// conv0 fused BN stats
__device__ float    g_cs [256];
__device__ float    g_cs2[256];
// CSR
__device__ int      g_deg[100352];
__device__ int      g_scan[100352];
__device__ int      g_bsum[SCAN_B];
__device__ int      g_off[100001];
__device__ int      g_cur[100000];
__device__ int      g_srcs[600000];

__device__ __forceinline__ unsigned f2tf(float x) {
    unsigned r;
    asm("cvt.rna.tf32.f32 %0, %1;" : "=r"(r) : "f"(x));
    return r;
}

__device__ __forceinline__ void cpa16(void* dst, const void* src, bool pred) {
    unsigned d = (unsigned)__cvta_generic_to_shared(dst);
    int sz = pred ? 16 : 0;
    asm volatile("cp.async.cg.shared.global [%0], [%1], 16, %2;\n" :: "r"(d), "l"(src), "r"(sz));
}
__device__ __forceinline__ void cpa4(void* dst, const void* src, bool pred) {
    unsigned d = (unsigned)__cvta_generic_to_shared(dst);
    int sz = pred ? 4 : 0;
    asm volatile("cp.async.ca.shared.global [%0], [%1], 4, %2;\n" :: "r"(d), "l"(src), "r"(sz));
}

// ------------------------- init: zero stats + degree -------------------------
__global__ void zero_kernel() {
    int i = blockIdx.x * blockDim.x + threadIdx.x;
    if (i < 256)  { g_cs[i] = 0.f; g_cs2[i] = 0.f; }
    if (i < 100352) g_deg[i] = 0;
}

// ------------------------- conv0: direct 3x3x3, C_in=4 + fused BN stats --------------
__global__ void conv0_kernel(const float* __restrict__ x, const float* __restrict__ w0) {
    __shared__ float ws[108];
    __shared__ float r1[256], r2[256];
    int co = blockIdx.y, b = blockIdx.z;
    if (threadIdx.x < 108) ws[threadIdx.x] = w0[co * 108 + threadIdx.x];
    __syncthreads();
    int s = blockIdx.x * 256 + threadIdx.x;
    int z = s >> 10, y = (s >> 5) & 31, xx = s & 31;
    float acc = 0.f;
    #pragma unroll
    for (int ci = 0; ci < 4; ci++) {
        const float* xb = x + ((size_t)(b * 4 + ci) << 15);
        const float* wc = ws + ci * 27;
        #pragma unroll
        for (int kd = 0; kd < 3; kd++) {
            int id = z + kd - 1;
            if ((unsigned)id > 31u) continue;
            #pragma unroll
            for (int kh = 0; kh < 3; kh++) {
                int ih = y + kh - 1;
                if ((unsigned)ih > 31u) continue;
                #pragma unroll
                for (int kw = 0; kw < 3; kw++) {
                    int iw = xx + kw - 1;
                    if ((unsigned)iw > 31u) continue;
                    acc = fmaf(xb[(id << 10) + (ih << 5) + iw], wc[kd * 9 + kh * 3 + kw], acc);
                }
            }
        }
    }
    g_f0[(((size_t)((b << 8) + co)) << 15) + s] = acc;
    // fused channel stats
    int tid = threadIdx.x;
    r1[tid] = acc; r2[tid] = acc * acc; __syncthreads();
    for (int o = 128; o; o >>= 1) {
        if (tid < o) { r1[tid] += r1[tid + o]; r2[tid] += r2[tid + o]; }
        __syncthreads();
    }
    if (tid == 0) {
        atomicAdd(&g_cs[co],  r1[0]);
        atomicAdd(&g_cs2[co], r2[0]);
    }
}

__global__ void bn0_final(const float* __restrict__ gm, const float* __restrict__ bt) {
    int c = threadIdx.x;                 // 256
    float inv = 1.f / 65536.f;
    float mean = g_cs[c] * inv;
    float var  = g_cs2[c] * inv - mean * mean;
    float sc = gm[c] * rsqrtf(var + 1e-5f);
    g_scale[c] = sc;
    g_shift[c] = bt[c] - mean * sc;
}

// ------------------------- batchnorm (conv1/conv2) -------------------------
__global__ void bn_stats_rc(const float* __restrict__ x, int C, int rows,
                            const float* __restrict__ gm, const float* __restrict__ bt) {
    int c = blockIdx.x;
    double s1 = 0.0, s2 = 0.0;
    for (int r = threadIdx.x; r < rows; r += blockDim.x) {
        float v = x[(size_t)r * C + c];
        s1 += v; s2 += (double)v * v;
    }
    __shared__ double r1[256], r2[256];
    int tid = threadIdx.x;
    r1[tid] = s1; r2[tid] = s2; __syncthreads();
    for (int o = 128; o; o >>= 1) {
        if (tid < o) { r1[tid] += r1[tid + o]; r2[tid] += r2[tid + o]; }
        __syncthreads();
    }
    if (tid == 0) {
        double mean = r1[0] / rows;
        double var  = r2[0] / rows - mean * mean;
        float sc = gm[c] * rsqrtf((float)var + 1e-5f);
        g_scale[c] = sc;
        g_shift[c] = bt[c] - (float)mean * sc;
    }
}

// bn-apply tf32, layout (b,c,s), float4 (S multiple of 4)
__global__ void bn_apply_bcs_t(const float* __restrict__ x, unsigned* __restrict__ o,
                               int C, int S, int n4, int do_relu) {
    int i = blockIdx.x * blockDim.x + threadIdx.x;
    if (i >= n4) return;
    int c = ((i * 4) / S) % C;
    float sc = g_scale[c], sh = g_shift[c];
    float4 v = ((const float4*)x)[i];
    v.x = v.x * sc + sh; v.y = v.y * sc + sh; v.z = v.z * sc + sh; v.w = v.w * sc + sh;
    if (do_relu) {
        v.x = fmaxf(v.x, 0.f); v.y = fmaxf(v.y, 0.f);
        v.z = fmaxf(v.z, 0.f); v.w = fmaxf(v.w, 0.f);
    }
    uint4 u; u.x = f2tf(v.x); u.y = f2tf(v.y); u.z = f2tf(v.z); u.w = f2tf(v.w);
    ((uint4*)o)[i] = u;
}

// bn-apply tf32, layout (rows, C), float4 (C multiple of 4)
__global__ void bn_apply_rc_t(const float* __restrict__ x, unsigned* __restrict__ o,
                              int C, int n4, int do_relu) {
    int i = blockIdx.x * blockDim.x + threadIdx.x;
    if (i >= n4) return;
    int c = (i * 4) % C;
    float4 v = ((const float4*)x)[i];
    v.x = v.x * g_scale[c]     + g_shift[c];
    v.y = v.y * g_scale[c + 1] + g_shift[c + 1];
    v.z = v.z * g_scale[c + 2] + g_shift[c + 2];
    v.w = v.w * g_scale[c + 3] + g_shift[c + 3];
    if (do_relu) {
        v.x = fmaxf(v.x, 0.f); v.y = fmaxf(v.y, 0.f);
        v.z = fmaxf(v.z, 0.f); v.w = fmaxf(v.w, 0.f);
    }
    uint4 u; u.x = f2tf(v.x); u.y = f2tf(v.y); u.z = f2tf(v.z); u.w = f2tf(v.w);
    ((uint4*)o)[i] = u;
}

// ------------------------- weight prep -------------------------
__global__ void transpose_t(const float* __restrict__ src, unsigned* __restrict__ dst,
                            int R, int Ccols) {
    __shared__ float tile[32][33];
    int c0 = blockIdx.x * 32, r0 = blockIdx.y * 32;
    int x = threadIdx.x, y = threadIdx.y;
    for (int i = y; i < 32; i += 8) {
        int r = r0 + i, c = c0 + x;
        tile[i][x] = (r < R && c < Ccols) ? src[(size_t)r * Ccols + c] : 0.f;
    }
    __syncthreads();
    for (int i = y; i < 32; i += 8) {
        int c = c0 + i, r = r0 + x;
        if (c < Ccols && r < R) dst[(size_t)c * R + r] = f2tf(tile[x][i]);
    }
}

__global__ void concat_w_t(const float* __restrict__ src, unsigned* __restrict__ dst,
                           int rowOff, int Kin, int Kpad, int F, int off, int Nout) {
    int i = blockIdx.x * blockDim.x + threadIdx.x;
    if (i >= Kpad * F) return;
    int k = i / F, f = i - k * F;
    float v = (k < Kin) ? src[(size_t)(k + rowOff) * F + f] : 0.f;
    dst[(size_t)k * Nout + off + f] = f2tf(v);
}

__global__ void copy_rows(const float* __restrict__ src, float* __restrict__ dst,
                          int rows, int F, int off, int Nout) {
    int i = blockIdx.x * blockDim.x + threadIdx.x;
    if (i >= rows * F) return;
    int k = i / F, f = i - k * F;
    dst[(size_t)k * Nout + off + f] = src[(size_t)k * F + f];
}

__global__ void build_bias(const float* __restrict__ src, float* __restrict__ dst,
                           int off, int F, int Nout) {
    int i = blockIdx.x * blockDim.x + threadIdx.x;
    if (i >= Nout) return;
    dst[i] = (i >= off && i < off + F) ? src[i - off] : 0.f;
}

// ------------------------- CSR build -------------------------
__global__ void hist_kernel(const int* __restrict__ ei) {
    int j = blockIdx.x * blockDim.x + threadIdx.x;
    if (j >= NE2) return;
    int b = (j >= NEDGES) ? 1 : 0;
    int e = j - b * NEDGES;
    int dst = __ldg(ei + NEDGES + e) + b * NNODES;
    atomicAdd(&g_deg[dst], 1);
}

__global__ void scan1_kernel() {
    __shared__ int tmp[1024];
    int tid = threadIdx.x;
    int gid = blockIdx.x * 1024 + tid;
    int v = (gid < NTOT) ? g_deg[gid] : 0;
    tmp[tid] = v;
    __syncthreads();
    for (int o = 1; o < 1024; o <<= 1) {
        int t = (tid >= o) ? tmp[tid - o] : 0;
        __syncthreads();
        tmp[tid] += t;
        __syncthreads();
    }
    g_scan[gid] = tmp[tid] - v;          // exclusive within block
    if (tid == 1023) g_bsum[blockIdx.x] = tmp[1023];
}

__global__ void scan2_kernel() {
    if (threadIdx.x == 0) {
        int run = 0;
        for (int i = 0; i < SCAN_B; i++) { int t = g_bsum[i]; g_bsum[i] = run; run += t; }
        g_off[NTOT] = NE2;
    }
}

__global__ void scan3_kernel() {
    int gid = blockIdx.x * 1024 + threadIdx.x;
    if (gid >= NTOT) return;
    int o = g_scan[gid] + g_bsum[blockIdx.x];
    g_off[gid] = o;
    g_cur[gid] = o;
}

__global__ void fill_kernel(const int* __restrict__ ei) {
    int j = blockIdx.x * blockDim.x + threadIdx.x;
    if (j >= NE2) return;
    int b = (j >= NEDGES) ? 1 : 0;
    int e = j - b * NEDGES;
    int src = __ldg(ei + e) + b * NNODES;
    int dst = __ldg(ei + NEDGES + e) + b * NNODES;
    int pos = atomicAdd(&g_cur[dst], 1);
    g_srcs[pos] = src;
}

// ------------------------- tf32 tensor-core GEMM (cp.async 2-stage) -------------------------
#define ASD(s,m,k) sA[(s) * 4608 + (m) * 36 + (k)]
#define BSD(s,k,n) sB[(s) * 4352 + (k) * 136 + (n)]
template<int MODE>
__global__ void __launch_bounds__(256)
mma_gemm(const unsigned* __restrict__ A, const unsigned* __restrict__ Bm,
         float* __restrict__ C, int M, int N, int K, int lda,
         const float* __restrict__ bias, int do_relu) {
    extern __shared__ unsigned sm_raw[];
    unsigned* sA = sm_raw;
    unsigned* sB = sm_raw + 9216;
    int tid = threadIdx.x;
    int bm = blockIdx.y * 128, bn = blockIdx.x * 128;
    int warp = tid >> 5, lane = tid & 31;
    int wm = warp & 3, wn = warp >> 2;
    int g = lane >> 2, t4 = lane & 3;

    float c[2][8][4];
    #pragma unroll
    for (int i = 0; i < 2; i++)
        #pragma unroll
        for (int j = 0; j < 8; j++)
            #pragma unroll
            for (int r = 0; r < 4; r++) c[i][j][r] = 0.f;

    int ntiles = K >> 5;

    auto load_tile = [&](int s, int k0) {
        if (MODE == 0) {
            int m = tid >> 1, half = tid & 1;
            int gm = bm + m;
            bool ok = gm < M;
            const unsigned* arow = A + (size_t)gm * lda + k0;
            #pragma unroll
            for (int i = 0; i < 2; i++) {
                int kof = half * 16 + i * 8;
                cpa16(&ASD(s, m, kof),     ok ? (arow + kof)     : A, ok);
                cpa16(&ASD(s, m, kof + 4), ok ? (arow + kof + 4) : A, ok);
            }
        } else {
            #pragma unroll
            for (int j = 0; j < 16; j++) {
                int l = tid * 16 + j;
                int m = l >> 5, kk = l & 31;
                int gm = bm + m, gk = k0 + kk;
                size_t idx = 0; bool ok = false;
                if (MODE == 1) {
                    int b = gm >> 12, ss = gm & 4095;
                    int od = ss >> 8, oh = (ss >> 4) & 15, ow = ss & 15;
                    int cc = gk >> 6, r = gk & 63;
                    int kd = r >> 4, kh = (r >> 2) & 3, kw = r & 3;
                    int id = od * 2 - 1 + kd, ih = oh * 2 - 1 + kh, iw = ow * 2 - 1 + kw;
                    ok = (unsigned)id <= 31u && (unsigned)ih <= 31u && (unsigned)iw <= 31u;
                    idx = (((size_t)((b << 8) + cc)) << 15) + (id << 10) + (ih << 5) + iw;
                } else {
                    int b = gm >> 12, ss = gm & 4095;
                    int od = ss >> 8, oh = (ss >> 4) & 15, ow = ss & 15;
                    int cc = gk / 27, r = gk - cc * 27;
                    int kd = r / 9; r -= kd * 9;
                    int kh = r / 3; int kw = r - kh * 3;
                    int id = od - 1 + kd, ih = oh - 1 + kh, iw = ow - 1 + kw;
                    ok = (unsigned)id <= 15u && (unsigned)ih <= 15u && (unsigned)iw <= 15u;
                    idx = ((size_t)((b << 12) + (id << 8) + (ih << 4) + iw)) * 512 + cc;
                }
                cpa4(&ASD(s, m, kk), ok ? (A + idx) : A, ok);
            }
        }
        {
            int kk = tid >> 3, quad = tid & 7;
            const unsigned* brow = Bm + (size_t)(k0 + kk) * N + bn;
            #pragma unroll
            for (int i = 0; i < 4; i++) {
                int n = quad * 16 + i * 4;
                bool ok = (bn + n) < N;
                cpa16(&BSD(s, kk, n), ok ? (brow + n) : Bm, ok);
            }
        }
        asm volatile("cp.async.commit_group;\n");
    };

    load_tile(0, 0);
    for (int t = 0; t < ntiles; t++) {
        int s = t & 1;
        if (t + 1 < ntiles) {
            load_tile(s ^ 1, (t + 1) << 5);
            asm volatile("cp.async.wait_group 1;\n");
        } else {
            asm volatile("cp.async.wait_group 0;\n");
        }
        __syncthreads();
        #pragma unroll
        for (int ks = 0; ks < 4; ks++) {
            int kb = ks * 8;
            unsigned a[2][4], b[8][2];
            #pragma unroll
            for (int mt = 0; mt < 2; mt++) {
                int m0 = wm * 32 + mt * 16;
                a[mt][0] = ASD(s, m0 + g,     kb + t4);
                a[mt][1] = ASD(s, m0 + g + 8, kb + t4);
                a[mt][2] = ASD(s, m0 + g,     kb + t4 + 4);
                a[mt][3] = ASD(s, m0 + g + 8, kb + t4 + 4);
            }
            #pragma unroll
            for (int nt = 0; nt < 8; nt++) {
                int n0 = wn * 64 + nt * 8;
                b[nt][0] = BSD(s, kb + t4,     n0 + g);
                b[nt][1] = BSD(s, kb + t4 + 4, n0 + g);
            }
            #pragma unroll
            for (int mt = 0; mt < 2; mt++)
                #pragma unroll
                for (int nt = 0; nt < 8; nt++) {
                    asm volatile(
                        "mma.sync.aligned.m16n8k8.row.col.f32.tf32.tf32.f32 "
                        "{%0,%1,%2,%3}, {%4,%5,%6,%7}, {%8,%9}, {%0,%1,%2,%3};"
                        : "+f"(c[mt][nt][0]), "+f"(c[mt][nt][1]),
                          "+f"(c[mt][nt][2]), "+f"(c[mt][nt][3])
                        : "r"(a[mt][0]), "r"(a[mt][1]), "r"(a[mt][2]), "r"(a[mt][3]),
                          "r"(b[nt][0]), "r"(b[nt][1]));
                }
        }
        __syncthreads();
    }
    #pragma unroll
    for (int mt = 0; mt < 2; mt++) {
        #pragma unroll
        for (int nt = 0; nt < 8; nt++) {
            int gn0 = bn + wn * 64 + nt * 8 + 2 * t4;
            #pragma unroll
            for (int r = 0; r < 4; r++) {
                int gm = bm + wm * 32 + mt * 16 + g + (r >> 1) * 8;
                int gn = gn0 + (r & 1);
                if (gm < M && gn < N) {
                    float v = c[mt][nt][r];
                    if (bias) v += bias[gn];
                    if (do_relu) v = fmaxf(v, 0.f);
                    C[(size_t)gm * N + gn] = v;
                }
            }
        }
    }
}

// ------------------------- per-node scatter: kqvs1 = voxout[vox] + pos*Wpos + bias ---------
__global__ void knode_kernel(const float* __restrict__ pos) {
    int r = blockIdx.x;
    int b = r / NNODES, n = r - b * NNODES;
    float p0 = pos[n * 3], p1 = pos[n * 3 + 1], p2 = pos[n * 3 + 2];
    int i0 = (int)(p0 * 16.f - 1.f);
    int i1 = (int)(p1 * 16.f - 1.f);
    int i2 = (int)(p2 * 16.f - 1.f);
    int vox = (i0 << 8) + (i1 << 4) + i2;
    const float4* vrow = (const float4*)(g_voxout + ((size_t)((b << 12) + vox)) * 1024);
    const float4* wr0  = (const float4*)(g_wpos1);
    const float4* wr1  = (const float4*)(g_wpos1 + 1024);
    const float4* wr2  = (const float4*)(g_wpos1 + 2048);
    const float4* br   = (const float4*)(g_bias1);
    float4* drow = (float4*)(g_kqvs1 + (size_t)r * 1024);
    int c = threadIdx.x;
    float4 v = vrow[c], w0 = wr0[c], w1 = wr1[c], w2 = wr2[c], bb = br[c];
    float4 o;
    o.x = v.x + p0 * w0.x + p1 * w1.x + p2 * w2.x + bb.x;
    o.y = v.y + p0 * w0.y + p1 * w1.y + p2 * w2.y + bb.y;
    o.z = v.z + p0 * w0.z + p1 * w1.z + p2 * w2.z + bb.z;
    o.w = v.w + p0 * w0.w + p1 * w1.w + p2 * w2.w + bb.w;
    drow[c] = o;
}

// ------------------------- CSR gated aggregation + relu + tf32 pack -------------------------
// row layout: [k | q | v | h] each F wide, stride 4F. One block per node, F threads.
template<int F>
__global__ void agg_kernel(const float* __restrict__ base, unsigned* __restrict__ packed) {
    int node = blockIdx.x;
    int c = threadIdx.x;
    const int stride = 4 * F;
    const float* nrow = base + (size_t)node * stride;
    float kv  = nrow[c];
    float acc = nrow[3 * F + c];          // x@Ws + bias (from GEMM/knode)
    int s0 = __ldg(&g_off[node]), s1 = __ldg(&g_off[node + 1]);
    for (int i = s0; i < s1; i++) {
        int src = __ldg(&g_srcs[i]);
        const float* srow = base + (size_t)src * stride;
        float qv = srow[F + c];
        float vv = srow[2 * F + c];
        acc += vv * (1.f / (1.f + __expf(-(kv + qv))));
    }
    packed[(size_t)node * F + c] = f2tf(fmaxf(acc, 0.f));
}

// ------------------------- final tiny layer (N=3) -------------------------
__global__ void mlp2_kernel(const float* __restrict__ w, const float* __restrict__ bb,
                            float* __restrict__ out) {
    int r = blockIdx.x * blockDim.x + threadIdx.x;
    if (r >= NTOT) return;
    const float* row = g_h3 + (size_t)r * 64;
    float a0 = bb[0], a1 = bb[1], a2 = bb[2];
    #pragma unroll
    for (int k = 0; k < 64; k++) {
        float xv = row[k];
        a0 = fmaf(xv, __ldg(&w[k * 3 + 0]), a0);
        a1 = fmaf(xv, __ldg(&w[k * 3 + 1]), a1);
        a2 = fmaf(xv, __ldg(&w[k * 3 + 2]), a2);
    }
    out[r * 3 + 0] = fmaxf(a0, 0.f);
    out[r * 3 + 1] = fmaxf(a1, 0.f);
    out[r * 3 + 2] = fmaxf(a2, 0.f);
}

// ------------------------- launcher -------------------------
extern "C" void kernel_launch(void* const* d_in, const int* in_sizes, int n_in,
                              void* d_out, int out_size) {
    const float* x   = (const float*)d_in[0];
    const float* pos = (const float*)d_in[1];
    const float* w0  = (const float*)d_in[2];
    const float* g0  = (const float*)d_in[3];
    const float* b0  = (const float*)d_in[4];
    const float* w1  = (const float*)d_in[5];
    const float* g1  = (const float*)d_in[6];
    const float* b1  = (const float*)d_in[7];
    const float* w2  = (const float*)d_in[8];
    const float* g2  = (const float*)d_in[9];
    const float* b2  = (const float*)d_in[10];
    const float* gk1 = (const float*)d_in[11];
    const float* gq1 = (const float*)d_in[12];
    const float* gv1 = (const float*)d_in[13];
    const float* gs1 = (const float*)d_in[14];
    const float* gb1 = (const float*)d_in[15];
    const float* gk2 = (const float*)d_in[16];
    const float* gq2 = (const float*)d_in[17];
    const float* gv2 = (const float*)d_in[18];
    const float* gs2 = (const float*)d_in[19];
    const float* gb2 = (const float*)d_in[20];
    const float* m1w = (const float*)d_in[21];
    const float* m1b = (const float*)d_in[22];
    const float* m2w = (const float*)d_in[23];
    const float* m2b = (const float*)d_in[24];
    const int*   ei  = (const int*)d_in[25];
    float* out = (float*)d_out;

    float    *p_f0, *p_f1, *p_f2, *p_wpos1, *p_bias1, *p_bias2;
    float    *p_voxout, *p_kqvs1, *p_kqvs2, *p_h3;
    unsigned *p_f0t, *p_f1t, *p_f2t, *p_w1t, *p_w2t, *p_wfeat1t, *p_wcat2t, *p_m1wt;
    unsigned *p_h1t, *p_h2t;
    cudaGetSymbolAddress((void**)&p_f0,      g_f0);
    cudaGetSymbolAddress((void**)&p_f0t,     g_f0t);
    cudaGetSymbolAddress((void**)&p_f1,      g_f1);
    cudaGetSymbolAddress((void**)&p_f1t,     g_f1t);
    cudaGetSymbolAddress((void**)&p_f2,      g_f2);
    cudaGetSymbolAddress((void**)&p_f2t,     g_f2t);
    cudaGetSymbolAddress((void**)&p_w1t,     g_w1t);
    cudaGetSymbolAddress((void**)&p_w2t,     g_w2t);
    cudaGetSymbolAddress((void**)&p_wfeat1t, g_wfeat1t);
    cudaGetSymbolAddress((void**)&p_wpos1,   g_wpos1);
    cudaGetSymbolAddress((void**)&p_bias1,   g_bias1);
    cudaGetSymbolAddress((void**)&p_wcat2t,  g_wcat2t);
    cudaGetSymbolAddress((void**)&p_bias2,   g_bias2);
    cudaGetSymbolAddress((void**)&p_m1wt,    g_m1wt);
    cudaGetSymbolAddress((void**)&p_voxout,  g_voxout);
    cudaGetSymbolAddress((void**)&p_kqvs1,   g_kqvs1);
    cudaGetSymbolAddress((void**)&p_h1t,     g_h1t);
    cudaGetSymbolAddress((void**)&p_kqvs2,   g_kqvs2);
    cudaGetSymbolAddress((void**)&p_h2t,     g_h2t);
    cudaGetSymbolAddress((void**)&p_h3,      g_h3);

    cudaFuncSetAttribute(mma_gemm<0>, cudaFuncAttributeMaxDynamicSharedMemorySize, SMEM_BYTES);
    cudaFuncSetAttribute(mma_gemm<1>, cudaFuncAttributeMaxDynamicSharedMemorySize, SMEM_BYTES);
    cudaFuncSetAttribute(mma_gemm<2>, cudaFuncAttributeMaxDynamicSharedMemorySize, SMEM_BYTES);

    // init
    zero_kernel<<<CDIV(100352, 256), 256>>>();

    // conv0 (+fused stats) + finalize + bn-apply -> tf32
    conv0_kernel<<<dim3(128, 256, 2), 256>>>(x, w0);
    bn0_final<<<1, 256>>>(g0, b0);
    bn_apply_bcs_t<<<CDIV(4194304, 256), 256>>>(p_f0, p_f0t, 256, 32768, 4194304, 1);

    // CSR build (depends only on ei)
    hist_kernel<<<CDIV(NE2, 256), 256>>>(ei);
    scan1_kernel<<<SCAN_B, 1024>>>();
    scan2_kernel<<<1, 32>>>();
    scan3_kernel<<<SCAN_B, 1024>>>();
    fill_kernel<<<CDIV(NE2, 256), 256>>>(ei);

    // weight prep
    transpose_t<<<dim3(16384 / 32, 512 / 32), dim3(32, 8)>>>(w1, p_w1t, 512, 16384);
    transpose_t<<<dim3(13824 / 32, 512 / 32), dim3(32, 8)>>>(w2, p_w2t, 512, 13824);
    concat_w_t<<<CDIV(512 * 256, 256), 256>>>(gk1, p_wfeat1t, 3, 512, 512, 256, 0,    1024);
    concat_w_t<<<CDIV(512 * 256, 256), 256>>>(gq1, p_wfeat1t, 3, 512, 512, 256, 256,  1024);
    concat_w_t<<<CDIV(512 * 256, 256), 256>>>(gv1, p_wfeat1t, 3, 512, 512, 256, 512,  1024);
    concat_w_t<<<CDIV(512 * 256, 256), 256>>>(gs1, p_wfeat1t, 3, 512, 512, 256, 768,  1024);
    copy_rows<<<3, 256>>>(gk1, p_wpos1, 3, 256, 0,   1024);
    copy_rows<<<3, 256>>>(gq1, p_wpos1, 3, 256, 256, 1024);
    copy_rows<<<3, 256>>>(gv1, p_wpos1, 3, 256, 512, 1024);
    copy_rows<<<3, 256>>>(gs1, p_wpos1, 3, 256, 768, 1024);
    concat_w_t<<<CDIV(256 * 128, 256), 256>>>(gk2, p_wcat2t, 0, 256, 256, 128, 0,   512);
    concat_w_t<<<CDIV(256 * 128, 256), 256>>>(gq2, p_wcat2t, 0, 256, 256, 128, 128, 512);
    concat_w_t<<<CDIV(256 * 128, 256), 256>>>(gv2, p_wcat2t, 0, 256, 256, 128, 256, 512);
    concat_w_t<<<CDIV(256 * 128, 256), 256>>>(gs2, p_wcat2t, 0, 256, 256, 128, 384, 512);
    concat_w_t<<<CDIV(128 * 64, 256), 256>>>(m1w, p_m1wt, 0, 128, 128, 64, 0, 64);
    build_bias<<<4, 256>>>(gb1, p_bias1, 768, 256, 1024);
    build_bias<<<2, 256>>>(gb2, p_bias2, 384, 128, 512);

    // conv1 + bn + relu -> tf32
    mma_gemm<1><<<dim3(4, 64), 256, SMEM_BYTES>>>(p_f0t, p_w1t, p_f1, 8192, 512, 16384, 0, nullptr, 0);
    bn_stats_rc<<<512, 256>>>(p_f1, 512, 8192, g1, b1);
    bn_apply_rc_t<<<CDIV(1048576, 256), 256>>>(p_f1, p_f1t, 512, 1048576, 1);

    // conv2 + bn -> tf32
    mma_gemm<2><<<dim3(4, 64), 256, SMEM_BYTES>>>(p_f1t, p_w2t, p_f2, 8192, 512, 13824, 0, nullptr, 0);
    bn_stats_rc<<<512, 256>>>(p_f2, 512, 8192, g2, b2);
    bn_apply_rc_t<<<CDIV(1048576, 256), 256>>>(p_f2, p_f2t, 512, 1048576, 0);

    // voxel-level GNN1 GEMM: (8192,512) @ (512,1024)
    mma_gemm<0><<<dim3(8, 64), 256, SMEM_BYTES>>>(p_f2t, p_wfeat1t, p_voxout,
                                                  8192, 1024, 512, 512, nullptr, 0);
    knode_kernel<<<NTOT, 256>>>(pos);

    // GNN layer 1: CSR aggregation + relu + pack
    agg_kernel<256><<<NTOT, 256>>>(p_kqvs1, p_h1t);

    // GNN layer 2
    mma_gemm<0><<<dim3(4, CDIV(NTOT, 128)), 256, SMEM_BYTES>>>(p_h1t, p_wcat2t, p_kqvs2,
                                                               NTOT, 512, 256, 256, p_bias2, 0);
    agg_kernel<128><<<NTOT, 128>>>(p_kqvs2, p_h2t);

    // MLP head
    mma_gemm<0><<<dim3(1, CDIV(NTOT, 128)), 256, SMEM_BYTES>>>(p_h2t, p_m1wt, p_h3,
                                                               NTOT, 64, 128, 128, m1b, 1);
    mlp2_kernel<<<CDIV(NTOT, 256), 256>>>(m2w, m2b, out);
}